// round 11
// baseline (speedup 1.0000x reference)
#include <cuda_runtime.h>
#include <cuda_fp16.h>
#include <cstdint>
#include <cfloat>
#include <math_constants.h>

#define Bev 128
#define Pn  200
#define Kn  60
#define Hd  64
#define Nn  (Bev*Pn)          // 25600
#define En  (Nn*Kn)           // 1,536,000

// ---------------- scratch (no cudaMalloc allowed) ----------------
__device__ __align__(16) float g_u[Nn*Hd];   // u = x@W1[:4] + pos@W1[4:] + b1
__device__ __align__(16) float g_v[Nn*Hd];   // v = pos@W1[4:]
__device__ int   g_nbr[En];                  // sorted knn neighbor ids

// ================= helpers =========================================
__device__ __forceinline__ uint32_t smem_u32(const void* p) {
    uint32_t a;
    asm("{ .reg .u64 t; cvta.to.shared.u64 t, %1; cvt.u32.u64 %0, t; }" : "=r"(a) : "l"(p));
    return a;
}
__device__ __forceinline__ void ldsm4(uint32_t* r, uint32_t addr) {
    asm volatile("ldmatrix.sync.aligned.m8n8.x4.shared.b16 {%0,%1,%2,%3}, [%4];"
        : "=r"(r[0]), "=r"(r[1]), "=r"(r[2]), "=r"(r[3]) : "r"(addr));
}
__device__ __forceinline__ void mma16816(float* d, const uint32_t* a, const uint32_t* b) {
    asm volatile("mma.sync.aligned.m16n8k16.row.col.f32.f16.f16.f32 "
        "{%0,%1,%2,%3}, {%4,%5,%6,%7}, {%8,%9}, {%0,%1,%2,%3};"
        : "+f"(d[0]), "+f"(d[1]), "+f"(d[2]), "+f"(d[3])
        : "r"(a[0]), "r"(a[1]), "r"(a[2]), "r"(a[3]), "r"(b[0]), "r"(b[1]));
}
__device__ __forceinline__ uint32_t pkh2(__half a, __half b) {
    __half2 t = __halves2half2(a, b);
    return *reinterpret_cast<uint32_t*>(&t);
}
__device__ __forceinline__ void cpa16(uint32_t dst, const void* src) {
    asm volatile("cp.async.cg.shared.global [%0], [%1], 16;" :: "r"(dst), "l"(src));
}

// ------- kernel 1: fused uv precompute + exact knn (sorted top-60) -------
// Branchless FMNMX bubble-insertion: every candidate is inserted via a
// min/max bubble pass (worse-than-kth candidates fall off the end).
// Keys on the predicate-free FMNMX path; 1 FSETP + 2 SEL for the index.
// Ascending-j scan + strict < == stable (d2 asc, idx asc) — identical
// selection bits to the prior passing kernels.
__global__ void __launch_bounds__(256, 1)
knn_kernel(const float* __restrict__ pos, const float* __restrict__ x,
           const float* __restrict__ W1, const float* __restrict__ b1,
           float* __restrict__ out,
           int write_aux, long long off_pos, long long off_batch, long long off_edge) {
    __shared__ float spx[Pn], spy[Pn], spz[Pn];
    __shared__ float sW1[7*64];
    __shared__ float sb1[64];
    int b = blockIdx.x;
    int tid = threadIdx.x;
    for (int t = tid; t < Pn; t += 256) {
        spx[t] = pos[(b*Pn+t)*3+0];
        spy[t] = pos[(b*Pn+t)*3+1];
        spz[t] = pos[(b*Pn+t)*3+2];
    }
    for (int t = tid; t < 7*64; t += 256) sW1[t] = W1[t];
    if (tid < 64) sb1[tid] = b1[tid];
    __syncthreads();

    // ---- uv for this event's 200 nodes ----
    for (int e = tid; e < Pn*64; e += 256) {
        int n = e >> 6, c = e & 63;
        int gn = b*Pn + n;
        float4 xv = *(const float4*)(x + (size_t)gn*4);
        float a = sb1[c];
        a = fmaf(xv.x, sW1[0*64+c], a);
        a = fmaf(xv.y, sW1[1*64+c], a);
        a = fmaf(xv.z, sW1[2*64+c], a);
        a = fmaf(xv.w, sW1[3*64+c], a);
        float vv = spx[n] * sW1[4*64+c];
        vv = fmaf(spy[n], sW1[5*64+c], vv);
        vv = fmaf(spz[n], sW1[6*64+c], vv);
        g_u[(size_t)b*Pn*64 + e] = a + vv;
        g_v[(size_t)b*Pn*64 + e] = vv;
    }

    if (tid >= Pn) return;
    int i  = tid;
    int gi = b*Pn + i;
    float pix = spx[i], piy = spy[i], piz = spz[i];

    float key[Kn];
    int   idx[Kn];
#pragma unroll
    for (int t = 0; t < Kn; t++) { key[t] = CUDART_INF_F; idx[t] = 0; }

    for (int j = 0; j < Pn; j++) {
        float dx = spx[j]-pix, dy = spy[j]-piy, dz = spz[j]-piz;
        float d2 = dx*dx; d2 = fmaf(dy,dy,d2); d2 = fmaf(dz,dz,d2);
        float ck = (j == i) ? CUDART_INF_F : d2;   // self bubbles off the end
        int   ci = j;
#pragma unroll
        for (int t = 0; t < Kn; t++) {
            float sk = key[t];
            bool  p  = ck < sk;
            float lo = fminf(ck, sk);
            float hi = fmaxf(ck, sk);
            int   si = idx[t];
            key[t] = lo;
            idx[t] = p ? ci : si;
            ci     = p ? si : ci;
            ck     = hi;
        }
    }
#pragma unroll
    for (int t = 0; t < Kn; t++) {
        int j = idx[t];
        g_nbr[gi*Kn + t] = b*Pn + j;
        if (write_aux) {
            out[off_edge +       (long long)gi*Kn + t] = (float)(b*Pn + j);
            out[off_edge + En +  (long long)gi*Kn + t] = (float)gi;
        }
    }
    if (write_aux) {
        out[off_pos + (long long)gi*3+0] = pix;
        out[off_pos + (long long)gi*3+1] = piy;
        out[off_pos + (long long)gi*3+2] = piz;
        out[off_batch + gi] = (float)b;
    }
}

// ---------------- kernel 2: HMMA mlp + fused max-aggregate --------
// (byte-exact round-10 version — known good at 152.2us)
__global__ void __launch_bounds__(128)
mlp3_kernel(const float* __restrict__ W2, const float* __restrict__ b2,
            float* __restrict__ out) {
    __shared__ __align__(16) __half sW[2][64][72];    // [hi/lo][ch][k]
    __shared__ __align__(16) float  sU[4][2][8][72];  // [warp][stage][row][64+pad]
    int tid = threadIdx.x, lane = tid & 31, warp = tid >> 5;

    for (int e = tid; e < 64*64; e += 128) {
        int k = e >> 6, ch = e & 63;
        float w = W2[k*64 + ch];
        __half hi = __float2half_rn(w);
        __half lo = __float2half_rn(w - __half2float(hi));
        sW[0][ch][k] = hi;
        sW[1][ch][k] = lo;
    }
    __syncthreads();

    // ldmatrix source coords (constant all kernel)
    const int r = (lane & 7) + ((lane >> 3) & 1) * 8;
    const int c = ((lane >> 4) & 1) * 8;

    // aH resident; aL reloaded per mt-tile in the loop
    uint32_t aH[4][4][4];
#pragma unroll
    for (int mt = 0; mt < 4; mt++)
#pragma unroll
        for (int kt = 0; kt < 4; kt++)
            ldsm4(aH[mt][kt], smem_u32(&sW[0][mt*16 + r][kt*16 + c]));

    int i = blockIdx.x * 4 + warp;                    // node id
    const int cb = (lane & 3) * 2;                    // k base within k-tile
    const int mrow = lane >> 2;                       // message row in group
    const int seg  = lane & 15;                       // 16B chunk within row
    const int hi4  = lane >> 4;                       // row parity for prefetch

    int nA = g_nbr[(size_t)i*Kn + lane];
    int nB = (lane < Kn - 32) ? g_nbr[(size_t)i*Kn + 32 + lane] : 0;

    const uint32_t suBase = smem_u32(&sU[warp][0][0][0]);   // stage stride 2304B

    float2 vA[4], vB[4];
#pragma unroll
    for (int kt = 0; kt < 4; kt++) {
        vA[kt] = *(const float2*)(g_v + (size_t)i*64 + kt*16 + cb);
        vB[kt] = *(const float2*)(g_v + (size_t)i*64 + kt*16 + cb + 8);
    }

    float rm0[4], rm1[4];
#pragma unroll
    for (int mt = 0; mt < 4; mt++) { rm0[mt] = -FLT_MAX; rm1[mt] = -FLT_MAX; }

#define PREFETCH_GRP(gg, st) do {                                            \
        _Pragma("unroll")                                                    \
        for (int it = 0; it < 4; it++) {                                     \
            int rr = 2*it + hi4;                                             \
            int mm = (gg)*8 + rr;                                            \
            int jj = (mm < 32) ? __shfl_sync(0xffffffffu, nA, mm)            \
                   : (mm < Kn) ? __shfl_sync(0xffffffffu, nB, mm - 32)       \
                   : i;                                                      \
            cpa16(suBase + (st)*2304 + rr*288 + seg*16,                      \
                  (const char*)g_u + (size_t)jj*256 + seg*16);               \
        }                                                                    \
        asm volatile("cp.async.commit_group;" ::: "memory");                 \
    } while (0)

    PREFETCH_GRP(0, 0);

    for (int g = 0; g < 8; g++) {                     // 8 groups of 8 messages
        if (g < 7) {
            PREFETCH_GRP(g+1, (g+1)&1);
            asm volatile("cp.async.wait_group 1;" ::: "memory");
        } else {
            asm volatile("cp.async.wait_group 0;" ::: "memory");
        }
        __syncwarp();

        const float* su = &sU[warp][g & 1][0][0];
        uint32_t bH[4][2], bL[4][2];
#pragma unroll
        for (int kt = 0; kt < 4; kt++) {
            float2 uA = *(const float2*)(su + mrow*72 + kt*16 + cb);
            float2 uB = *(const float2*)(su + mrow*72 + kt*16 + cb + 8);
            float h0 = fmaxf(uA.x - vA[kt].x, 0.f);
            float h1 = fmaxf(uA.y - vA[kt].y, 0.f);
            float h2 = fmaxf(uB.x - vB[kt].x, 0.f);
            float h3 = fmaxf(uB.y - vB[kt].y, 0.f);
            __half q0 = __float2half_rn(h0), q1 = __float2half_rn(h1);
            __half q2 = __float2half_rn(h2), q3 = __float2half_rn(h3);
            bH[kt][0] = pkh2(q0, q1);
            bH[kt][1] = pkh2(q2, q3);
            bL[kt][0] = pkh2(__float2half_rn(h0 - __half2float(q0)),
                             __float2half_rn(h1 - __half2float(q1)));
            bL[kt][1] = pkh2(__float2half_rn(h2 - __half2float(q2)),
                             __float2half_rn(h3 - __half2float(q3)));
        }

#pragma unroll
        for (int mt = 0; mt < 4; mt++) {
            // reload aL for this tile only (short live range)
            uint32_t aLt[4][4];
#pragma unroll
            for (int kt = 0; kt < 4; kt++)
                ldsm4(aLt[kt], smem_u32(&sW[1][mt*16 + r][kt*16 + c]));

            float dh[4] = {0,0,0,0}, dl[4] = {0,0,0,0}, da[4] = {0,0,0,0};
#pragma unroll
            for (int kt = 0; kt < 4; kt++) {
                mma16816(dh, aH[mt][kt], bH[kt]);
                mma16816(dl, aH[mt][kt], bL[kt]);
                mma16816(da, aLt[kt],    bH[kt]);
            }
            float d0 = dh[0] + dl[0] + da[0];
            float d1 = dh[1] + dl[1] + da[1];
            float d2 = dh[2] + dl[2] + da[2];
            float d3 = dh[3] + dl[3] + da[3];
            rm0[mt] = fmaxf(rm0[mt], fmaxf(d0, d1));
            rm1[mt] = fmaxf(rm1[mt], fmaxf(d2, d3));
        }
        __syncwarp();   // reads of this stage done before next prefetch lands
    }

#pragma unroll
    for (int mt = 0; mt < 4; mt++) {
        rm0[mt] = fmaxf(rm0[mt], __shfl_xor_sync(0xffffffffu, rm0[mt], 1));
        rm0[mt] = fmaxf(rm0[mt], __shfl_xor_sync(0xffffffffu, rm0[mt], 2));
        rm1[mt] = fmaxf(rm1[mt], __shfl_xor_sync(0xffffffffu, rm1[mt], 1));
        rm1[mt] = fmaxf(rm1[mt], __shfl_xor_sync(0xffffffffu, rm1[mt], 2));
    }
    if ((lane & 3) == 0) {
        int rr = lane >> 2;
#pragma unroll
        for (int mt = 0; mt < 4; mt++) {
            int ch = mt*16 + rr;
            out[(size_t)i*64 + ch]     = fmaxf(rm0[mt] + b2[ch],     0.f);
            out[(size_t)i*64 + ch + 8] = fmaxf(rm1[mt] + b2[ch + 8], 0.f);
        }
    }
}

// ---------------- launcher ----------------------------------------
extern "C" void kernel_launch(void* const* d_in, const int* in_sizes, int n_in,
                              void* d_out, int out_size) {
    const float* x   = (const float*)d_in[0];
    const float* pos = (const float*)d_in[1];
    // d_in[2] = batch (int32) — recomputed analytically
    const float* W1  = (const float*)d_in[3];
    const float* b1  = (const float*)d_in[4];
    const float* W2  = (const float*)d_in[5];
    const float* b2  = (const float*)d_in[6];
    float* out = (float*)d_out;

    long long off_pos   = (long long)Nn * Hd;
    long long off_batch = off_pos + (long long)Nn * 3;
    long long off_edge  = off_batch + Nn;
    long long need      = off_edge + 2LL * En;
    int write_aux = ((long long)out_size >= need) ? 1 : 0;

    knn_kernel<<<Bev, 256>>>(pos, x, W1, b1, out, write_aux, off_pos, off_batch, off_edge);
    mlp3_kernel<<<Nn / 4, 128>>>(W2, b2, out);
}

// round 12
// speedup vs baseline: 1.0418x; 1.0418x over previous
#include <cuda_runtime.h>
#include <cuda_fp16.h>
#include <cstdint>
#include <cfloat>
#include <math_constants.h>

#define Bev 128
#define Pn  200
#define Kn  60
#define Hd  64
#define Nn  (Bev*Pn)          // 25600
#define En  (Nn*Kn)           // 1,536,000
#define TPB 25                // targets per knn block (8 blocks/event)

// ---------------- scratch (no cudaMalloc allowed) ----------------
__device__ __align__(16) float g_u[Nn*Hd];   // u = x@W1[:4] + pos@W1[4:] + b1
__device__ __align__(16) float g_v[Nn*Hd];   // v = pos@W1[4:]
__device__ int   g_nbr[En];                  // sorted knn neighbor ids

// ================= helpers =========================================
__device__ __forceinline__ uint32_t smem_u32(const void* p) {
    uint32_t a;
    asm("{ .reg .u64 t; cvta.to.shared.u64 t, %1; cvt.u32.u64 %0, t; }" : "=r"(a) : "l"(p));
    return a;
}
__device__ __forceinline__ void ldsm4(uint32_t* r, uint32_t addr) {
    asm volatile("ldmatrix.sync.aligned.m8n8.x4.shared.b16 {%0,%1,%2,%3}, [%4];"
        : "=r"(r[0]), "=r"(r[1]), "=r"(r[2]), "=r"(r[3]) : "r"(addr));
}
__device__ __forceinline__ void mma16816(float* d, const uint32_t* a, const uint32_t* b) {
    asm volatile("mma.sync.aligned.m16n8k16.row.col.f32.f16.f16.f32 "
        "{%0,%1,%2,%3}, {%4,%5,%6,%7}, {%8,%9}, {%0,%1,%2,%3};"
        : "+f"(d[0]), "+f"(d[1]), "+f"(d[2]), "+f"(d[3])
        : "r"(a[0]), "r"(a[1]), "r"(a[2]), "r"(a[3]), "r"(b[0]), "r"(b[1]));
}
__device__ __forceinline__ uint32_t pkh2(__half a, __half b) {
    __half2 t = __halves2half2(a, b);
    return *reinterpret_cast<uint32_t*>(&t);
}
__device__ __forceinline__ void cpa16(uint32_t dst, const void* src) {
    asm volatile("cp.async.cg.shared.global [%0], [%1], 16;" :: "r"(dst), "l"(src));
}

// ------- kernel 1: fused uv + split-scan exact knn (sorted top-60) -------
// 8 blocks/event x 64 threads; 25 targets/block; 2 scan threads per target,
// each runs the R10 guarded-shift over a disjoint 100-candidate half, then
// an exact stable 2-list merge (<= prefers low-j list) -> selection bits
// identical to the R10 single-thread scan.
__global__ void __launch_bounds__(64, 1)
knn_kernel(const float* __restrict__ pos, const float* __restrict__ x,
           const float* __restrict__ W1, const float* __restrict__ b1,
           float* __restrict__ out,
           int write_aux, long long off_pos, long long off_batch, long long off_edge) {
    __shared__ float spx[Pn], spy[Pn], spz[Pn];
    __shared__ float sW1[7*64];
    __shared__ float sb1[64];
    __shared__ float smK[TPB][2][Kn];
    __shared__ int   smI[TPB][2][Kn];
    int blk = blockIdx.x;
    int b   = blk >> 3;                // event
    int q   = blk & 7;                 // 25-target group
    int tid = threadIdx.x;

    for (int t = tid; t < Pn; t += 64) {
        spx[t] = pos[(b*Pn+t)*3+0];
        spy[t] = pos[(b*Pn+t)*3+1];
        spz[t] = pos[(b*Pn+t)*3+2];
    }
    for (int t = tid; t < 7*64; t += 64) sW1[t] = W1[t];
    if (tid < 64) sb1[tid] = b1[tid];
    __syncthreads();

    // ---- uv for this block's 25 nodes ----
    for (int e = tid; e < TPB*64; e += 64) {
        int nl = e >> 6, c = e & 63;
        int n  = q*TPB + nl;
        int gn = b*Pn + n;
        float4 xv = *(const float4*)(x + (size_t)gn*4);
        float a = sb1[c];
        a = fmaf(xv.x, sW1[0*64+c], a);
        a = fmaf(xv.y, sW1[1*64+c], a);
        a = fmaf(xv.z, sW1[2*64+c], a);
        a = fmaf(xv.w, sW1[3*64+c], a);
        float vv = spx[n] * sW1[4*64+c];
        vv = fmaf(spy[n], sW1[5*64+c], vv);
        vv = fmaf(spz[n], sW1[6*64+c], vv);
        g_u[(size_t)gn*64 + c] = a + vv;
        g_v[(size_t)gn*64 + c] = vv;
    }

    // ---- phase 1: split scan (tid < 50; tgt = tid>>1, half = tid&1) ----
    if (tid < 2*TPB) {
        int tgt  = tid >> 1;
        int half = tid & 1;
        int i    = q*TPB + tgt;
        float pix = spx[i], piy = spy[i], piz = spz[i];

        float key[Kn];
        int   idx[Kn];
#pragma unroll
        for (int t = 0; t < Kn; t++) { key[t] = CUDART_INF_F; idx[t] = 0; }

        int j0 = half * 100;
        for (int jj = 0; jj < 100; jj++) {
            int j = j0 + jj;
            float dx = spx[j]-pix, dy = spy[j]-piy, dz = spz[j]-piz;
            float d2 = dx*dx; d2 = fmaf(dy,dy,d2); d2 = fmaf(dz,dz,d2);
            d2 = (j == i) ? CUDART_INF_F : d2;
            if (d2 < key[Kn-1]) {
#pragma unroll
                for (int t = Kn-1; t > 0; --t) {
                    bool pa = d2 < key[t-1];
                    bool pc = d2 < key[t];
                    key[t] = pa ? key[t-1] : (pc ? d2 : key[t]);
                    idx[t] = pa ? idx[t-1] : (pc ? j  : idx[t]);
                }
                bool p0 = d2 < key[0];
                idx[0] = p0 ? j  : idx[0];
                key[0] = p0 ? d2 : key[0];
            }
        }
#pragma unroll
        for (int t = 0; t < Kn; t++) {
            smK[tgt][half][t] = key[t];
            smI[tgt][half][t] = idx[t];
        }
    }
    __syncthreads();

    // ---- phase 2: exact stable merge (tid < 25) ----
    if (tid < TPB) {
        int tgt = tid;
        int i   = q*TPB + tgt;
        int gi  = b*Pn + i;
        int p0 = 0, p1 = 0;
        for (int t = 0; t < Kn; t++) {           // p0+p1 = t <= 59: no OOB
            float k0 = smK[tgt][0][p0];
            float k1 = smK[tgt][1][p1];
            bool take0 = (k0 <= k1);             // tie -> low-j list (stable)
            int jl = take0 ? smI[tgt][0][p0] : smI[tgt][1][p1];
            p0 += take0 ? 1 : 0;
            p1 += take0 ? 0 : 1;
            g_nbr[(size_t)gi*Kn + t] = b*Pn + jl;
            if (write_aux) {
                out[off_edge +      (long long)gi*Kn + t] = (float)(b*Pn + jl);
                out[off_edge + En + (long long)gi*Kn + t] = (float)gi;
            }
        }
        if (write_aux) {
            out[off_pos + (long long)gi*3+0] = spx[i];
            out[off_pos + (long long)gi*3+1] = spy[i];
            out[off_pos + (long long)gi*3+2] = spz[i];
            out[off_batch + gi] = (float)b;
        }
    }
}

// ---------------- kernel 2: HMMA mlp + fused max-aggregate --------
// (byte-exact round-10 version — known good at 152.2us)
__global__ void __launch_bounds__(128)
mlp3_kernel(const float* __restrict__ W2, const float* __restrict__ b2,
            float* __restrict__ out) {
    __shared__ __align__(16) __half sW[2][64][72];    // [hi/lo][ch][k]
    __shared__ __align__(16) float  sU[4][2][8][72];  // [warp][stage][row][64+pad]
    int tid = threadIdx.x, lane = tid & 31, warp = tid >> 5;

    for (int e = tid; e < 64*64; e += 128) {
        int k = e >> 6, ch = e & 63;
        float w = W2[k*64 + ch];
        __half hi = __float2half_rn(w);
        __half lo = __float2half_rn(w - __half2float(hi));
        sW[0][ch][k] = hi;
        sW[1][ch][k] = lo;
    }
    __syncthreads();

    // ldmatrix source coords (constant all kernel)
    const int r = (lane & 7) + ((lane >> 3) & 1) * 8;
    const int c = ((lane >> 4) & 1) * 8;

    // aH resident; aL reloaded per mt-tile in the loop
    uint32_t aH[4][4][4];
#pragma unroll
    for (int mt = 0; mt < 4; mt++)
#pragma unroll
        for (int kt = 0; kt < 4; kt++)
            ldsm4(aH[mt][kt], smem_u32(&sW[0][mt*16 + r][kt*16 + c]));

    int i = blockIdx.x * 4 + warp;                    // node id
    const int cb = (lane & 3) * 2;                    // k base within k-tile
    const int mrow = lane >> 2;                       // message row in group
    const int seg  = lane & 15;                       // 16B chunk within row
    const int hi4  = lane >> 4;                       // row parity for prefetch

    int nA = g_nbr[(size_t)i*Kn + lane];
    int nB = (lane < Kn - 32) ? g_nbr[(size_t)i*Kn + 32 + lane] : 0;

    const uint32_t suBase = smem_u32(&sU[warp][0][0][0]);   // stage stride 2304B

    float2 vA[4], vB[4];
#pragma unroll
    for (int kt = 0; kt < 4; kt++) {
        vA[kt] = *(const float2*)(g_v + (size_t)i*64 + kt*16 + cb);
        vB[kt] = *(const float2*)(g_v + (size_t)i*64 + kt*16 + cb + 8);
    }

    float rm0[4], rm1[4];
#pragma unroll
    for (int mt = 0; mt < 4; mt++) { rm0[mt] = -FLT_MAX; rm1[mt] = -FLT_MAX; }

#define PREFETCH_GRP(gg, st) do {                                            \
        _Pragma("unroll")                                                    \
        for (int it = 0; it < 4; it++) {                                     \
            int rr = 2*it + hi4;                                             \
            int mm = (gg)*8 + rr;                                            \
            int jj = (mm < 32) ? __shfl_sync(0xffffffffu, nA, mm)            \
                   : (mm < Kn) ? __shfl_sync(0xffffffffu, nB, mm - 32)       \
                   : i;                                                      \
            cpa16(suBase + (st)*2304 + rr*288 + seg*16,                      \
                  (const char*)g_u + (size_t)jj*256 + seg*16);               \
        }                                                                    \
        asm volatile("cp.async.commit_group;" ::: "memory");                 \
    } while (0)

    PREFETCH_GRP(0, 0);

    for (int g = 0; g < 8; g++) {                     // 8 groups of 8 messages
        if (g < 7) {
            PREFETCH_GRP(g+1, (g+1)&1);
            asm volatile("cp.async.wait_group 1;" ::: "memory");
        } else {
            asm volatile("cp.async.wait_group 0;" ::: "memory");
        }
        __syncwarp();

        const float* su = &sU[warp][g & 1][0][0];
        uint32_t bH[4][2], bL[4][2];
#pragma unroll
        for (int kt = 0; kt < 4; kt++) {
            float2 uA = *(const float2*)(su + mrow*72 + kt*16 + cb);
            float2 uB = *(const float2*)(su + mrow*72 + kt*16 + cb + 8);
            float h0 = fmaxf(uA.x - vA[kt].x, 0.f);
            float h1 = fmaxf(uA.y - vA[kt].y, 0.f);
            float h2 = fmaxf(uB.x - vB[kt].x, 0.f);
            float h3 = fmaxf(uB.y - vB[kt].y, 0.f);
            __half q0 = __float2half_rn(h0), q1 = __float2half_rn(h1);
            __half q2 = __float2half_rn(h2), q3 = __float2half_rn(h3);
            bH[kt][0] = pkh2(q0, q1);
            bH[kt][1] = pkh2(q2, q3);
            bL[kt][0] = pkh2(__float2half_rn(h0 - __half2float(q0)),
                             __float2half_rn(h1 - __half2float(q1)));
            bL[kt][1] = pkh2(__float2half_rn(h2 - __half2float(q2)),
                             __float2half_rn(h3 - __half2float(q3)));
        }

#pragma unroll
        for (int mt = 0; mt < 4; mt++) {
            // reload aL for this tile only (short live range)
            uint32_t aLt[4][4];
#pragma unroll
            for (int kt = 0; kt < 4; kt++)
                ldsm4(aLt[kt], smem_u32(&sW[1][mt*16 + r][kt*16 + c]));

            float dh[4] = {0,0,0,0}, dl[4] = {0,0,0,0}, da[4] = {0,0,0,0};
#pragma unroll
            for (int kt = 0; kt < 4; kt++) {
                mma16816(dh, aH[mt][kt], bH[kt]);
                mma16816(dl, aH[mt][kt], bL[kt]);
                mma16816(da, aLt[kt],    bH[kt]);
            }
            float d0 = dh[0] + dl[0] + da[0];
            float d1 = dh[1] + dl[1] + da[1];
            float d2 = dh[2] + dl[2] + da[2];
            float d3 = dh[3] + dl[3] + da[3];
            rm0[mt] = fmaxf(rm0[mt], fmaxf(d0, d1));
            rm1[mt] = fmaxf(rm1[mt], fmaxf(d2, d3));
        }
        __syncwarp();   // reads of this stage done before next prefetch lands
    }

#pragma unroll
    for (int mt = 0; mt < 4; mt++) {
        rm0[mt] = fmaxf(rm0[mt], __shfl_xor_sync(0xffffffffu, rm0[mt], 1));
        rm0[mt] = fmaxf(rm0[mt], __shfl_xor_sync(0xffffffffu, rm0[mt], 2));
        rm1[mt] = fmaxf(rm1[mt], __shfl_xor_sync(0xffffffffu, rm1[mt], 1));
        rm1[mt] = fmaxf(rm1[mt], __shfl_xor_sync(0xffffffffu, rm1[mt], 2));
    }
    if ((lane & 3) == 0) {
        int rr = lane >> 2;
#pragma unroll
        for (int mt = 0; mt < 4; mt++) {
            int ch = mt*16 + rr;
            out[(size_t)i*64 + ch]     = fmaxf(rm0[mt] + b2[ch],     0.f);
            out[(size_t)i*64 + ch + 8] = fmaxf(rm1[mt] + b2[ch + 8], 0.f);
        }
    }
}

// ---------------- launcher ----------------------------------------
extern "C" void kernel_launch(void* const* d_in, const int* in_sizes, int n_in,
                              void* d_out, int out_size) {
    const float* x   = (const float*)d_in[0];
    const float* pos = (const float*)d_in[1];
    // d_in[2] = batch (int32) — recomputed analytically
    const float* W1  = (const float*)d_in[3];
    const float* b1  = (const float*)d_in[4];
    const float* W2  = (const float*)d_in[5];
    const float* b2  = (const float*)d_in[6];
    float* out = (float*)d_out;

    long long off_pos   = (long long)Nn * Hd;
    long long off_batch = off_pos + (long long)Nn * 3;
    long long off_edge  = off_batch + Nn;
    long long need      = off_edge + 2LL * En;
    int write_aux = ((long long)out_size >= need) ? 1 : 0;

    knn_kernel<<<Bev*8, 64>>>(pos, x, W1, b1, out, write_aux, off_pos, off_batch, off_edge);
    mlp3_kernel<<<Nn / 4, 128>>>(W2, b2, out);
}

// round 13
// speedup vs baseline: 1.2466x; 1.1965x over previous
#include <cuda_runtime.h>
#include <cuda_fp16.h>
#include <cstdint>
#include <cfloat>
#include <math_constants.h>

#define Bev 128
#define Pn  200
#define Kn  60
#define Hd  64
#define Nn  (Bev*Pn)          // 25600
#define En  (Nn*Kn)           // 1,536,000
#define TPB 25                // targets per knn block (8 blocks/event)

// ---------------- scratch (no cudaMalloc allowed) ----------------
__device__ __align__(16) float g_u[Nn*Hd];   // u = x@W1[:4] + pos@W1[4:] + b1
__device__ __align__(16) float g_v[Nn*Hd];   // v = pos@W1[4:]
__device__ int   g_nbr[En];                  // sorted knn neighbor ids

// ================= helpers =========================================
__device__ __forceinline__ uint32_t smem_u32(const void* p) {
    uint32_t a;
    asm("{ .reg .u64 t; cvta.to.shared.u64 t, %1; cvt.u32.u64 %0, t; }" : "=r"(a) : "l"(p));
    return a;
}
__device__ __forceinline__ void ldsm4(uint32_t* r, uint32_t addr) {
    asm volatile("ldmatrix.sync.aligned.m8n8.x4.shared.b16 {%0,%1,%2,%3}, [%4];"
        : "=r"(r[0]), "=r"(r[1]), "=r"(r[2]), "=r"(r[3]) : "r"(addr));
}
__device__ __forceinline__ void mma16816(float* d, const uint32_t* a, const uint32_t* b) {
    asm volatile("mma.sync.aligned.m16n8k16.row.col.f32.f16.f16.f32 "
        "{%0,%1,%2,%3}, {%4,%5,%6,%7}, {%8,%9}, {%0,%1,%2,%3};"
        : "+f"(d[0]), "+f"(d[1]), "+f"(d[2]), "+f"(d[3])
        : "r"(a[0]), "r"(a[1]), "r"(a[2]), "r"(a[3]), "r"(b[0]), "r"(b[1]));
}
__device__ __forceinline__ uint32_t pkh2(__half a, __half b) {
    __half2 t = __halves2half2(a, b);
    return *reinterpret_cast<uint32_t*>(&t);
}
__device__ __forceinline__ void cpa16(uint32_t dst, const void* src) {
    asm volatile("cp.async.cg.shared.global [%0], [%1], 16;" :: "r"(dst), "l"(src));
}

// ------- kernel 1: fused uv + split-scan exact knn (sorted top-60) -------
// (byte-exact round-12 version — known good)
__global__ void __launch_bounds__(64, 1)
knn_kernel(const float* __restrict__ pos, const float* __restrict__ x,
           const float* __restrict__ W1, const float* __restrict__ b1,
           float* __restrict__ out,
           int write_aux, long long off_pos, long long off_batch, long long off_edge) {
    __shared__ float spx[Pn], spy[Pn], spz[Pn];
    __shared__ float sW1[7*64];
    __shared__ float sb1[64];
    __shared__ float smK[TPB][2][Kn];
    __shared__ int   smI[TPB][2][Kn];
    int blk = blockIdx.x;
    int b   = blk >> 3;                // event
    int q   = blk & 7;                 // 25-target group
    int tid = threadIdx.x;

    for (int t = tid; t < Pn; t += 64) {
        spx[t] = pos[(b*Pn+t)*3+0];
        spy[t] = pos[(b*Pn+t)*3+1];
        spz[t] = pos[(b*Pn+t)*3+2];
    }
    for (int t = tid; t < 7*64; t += 64) sW1[t] = W1[t];
    if (tid < 64) sb1[tid] = b1[tid];
    __syncthreads();

    // ---- uv for this block's 25 nodes ----
    for (int e = tid; e < TPB*64; e += 64) {
        int nl = e >> 6, c = e & 63;
        int n  = q*TPB + nl;
        int gn = b*Pn + n;
        float4 xv = *(const float4*)(x + (size_t)gn*4);
        float a = sb1[c];
        a = fmaf(xv.x, sW1[0*64+c], a);
        a = fmaf(xv.y, sW1[1*64+c], a);
        a = fmaf(xv.z, sW1[2*64+c], a);
        a = fmaf(xv.w, sW1[3*64+c], a);
        float vv = spx[n] * sW1[4*64+c];
        vv = fmaf(spy[n], sW1[5*64+c], vv);
        vv = fmaf(spz[n], sW1[6*64+c], vv);
        g_u[(size_t)gn*64 + c] = a + vv;
        g_v[(size_t)gn*64 + c] = vv;
    }

    // ---- phase 1: split scan (tid < 50; tgt = tid>>1, half = tid&1) ----
    if (tid < 2*TPB) {
        int tgt  = tid >> 1;
        int half = tid & 1;
        int i    = q*TPB + tgt;
        float pix = spx[i], piy = spy[i], piz = spz[i];

        float key[Kn];
        int   idx[Kn];
#pragma unroll
        for (int t = 0; t < Kn; t++) { key[t] = CUDART_INF_F; idx[t] = 0; }

        int j0 = half * 100;
        for (int jj = 0; jj < 100; jj++) {
            int j = j0 + jj;
            float dx = spx[j]-pix, dy = spy[j]-piy, dz = spz[j]-piz;
            float d2 = dx*dx; d2 = fmaf(dy,dy,d2); d2 = fmaf(dz,dz,d2);
            d2 = (j == i) ? CUDART_INF_F : d2;
            if (d2 < key[Kn-1]) {
#pragma unroll
                for (int t = Kn-1; t > 0; --t) {
                    bool pa = d2 < key[t-1];
                    bool pc = d2 < key[t];
                    key[t] = pa ? key[t-1] : (pc ? d2 : key[t]);
                    idx[t] = pa ? idx[t-1] : (pc ? j  : idx[t]);
                }
                bool p0 = d2 < key[0];
                idx[0] = p0 ? j  : idx[0];
                key[0] = p0 ? d2 : key[0];
            }
        }
#pragma unroll
        for (int t = 0; t < Kn; t++) {
            smK[tgt][half][t] = key[t];
            smI[tgt][half][t] = idx[t];
        }
    }
    __syncthreads();

    // ---- phase 2: exact stable merge (tid < 25) ----
    if (tid < TPB) {
        int tgt = tid;
        int i   = q*TPB + tgt;
        int gi  = b*Pn + i;
        int p0 = 0, p1 = 0;
        for (int t = 0; t < Kn; t++) {           // p0+p1 = t <= 59: no OOB
            float k0 = smK[tgt][0][p0];
            float k1 = smK[tgt][1][p1];
            bool take0 = (k0 <= k1);             // tie -> low-j list (stable)
            int jl = take0 ? smI[tgt][0][p0] : smI[tgt][1][p1];
            p0 += take0 ? 1 : 0;
            p1 += take0 ? 0 : 1;
            g_nbr[(size_t)gi*Kn + t] = b*Pn + jl;
            if (write_aux) {
                out[off_edge +      (long long)gi*Kn + t] = (float)(b*Pn + jl);
                out[off_edge + En + (long long)gi*Kn + t] = (float)gi;
            }
        }
        if (write_aux) {
            out[off_pos + (long long)gi*3+0] = spx[i];
            out[off_pos + (long long)gi*3+1] = spy[i];
            out[off_pos + (long long)gi*3+2] = spz[i];
            out[off_batch + gi] = (float)b;
        }
    }
}

// ---------------- kernel 2: HMMA mlp + fused max-aggregate --------
// 2-term fp16: D = aH*(bH+bL). The aL (W2 lo) term is dropped, spending
// rel_err budget (~3e-4 predicted vs 1e-3 threshold) to remove 1/3 of the
// MMAs and ALL aL ldmatrix reloads. Everything else identical to R10/R12.
__global__ void __launch_bounds__(128)
mlp3_kernel(const float* __restrict__ W2, const float* __restrict__ b2,
            float* __restrict__ out) {
    __shared__ __align__(16) __half sW[64][72];       // W2^T hi only
    __shared__ __align__(16) float  sU[4][2][8][72];  // [warp][stage][row][64+pad]
    int tid = threadIdx.x, lane = tid & 31, warp = tid >> 5;

    for (int e = tid; e < 64*64; e += 128) {
        int k = e >> 6, ch = e & 63;
        sW[ch][k] = __float2half_rn(W2[k*64 + ch]);
    }
    __syncthreads();

    // ldmatrix source coords (constant all kernel)
    const int r = (lane & 7) + ((lane >> 3) & 1) * 8;
    const int c = ((lane >> 4) & 1) * 8;

    // aH resident (64 regs); no aL anywhere
    uint32_t aH[4][4][4];
#pragma unroll
    for (int mt = 0; mt < 4; mt++)
#pragma unroll
        for (int kt = 0; kt < 4; kt++)
            ldsm4(aH[mt][kt], smem_u32(&sW[mt*16 + r][kt*16 + c]));

    int i = blockIdx.x * 4 + warp;                    // node id
    const int cb = (lane & 3) * 2;                    // k base within k-tile
    const int mrow = lane >> 2;                       // message row in group
    const int seg  = lane & 15;                       // 16B chunk within row
    const int hi4  = lane >> 4;                       // row parity for prefetch

    int nA = g_nbr[(size_t)i*Kn + lane];
    int nB = (lane < Kn - 32) ? g_nbr[(size_t)i*Kn + 32 + lane] : 0;

    const uint32_t suBase = smem_u32(&sU[warp][0][0][0]);   // stage stride 2304B

    float2 vA[4], vB[4];
#pragma unroll
    for (int kt = 0; kt < 4; kt++) {
        vA[kt] = *(const float2*)(g_v + (size_t)i*64 + kt*16 + cb);
        vB[kt] = *(const float2*)(g_v + (size_t)i*64 + kt*16 + cb + 8);
    }

    float rm0[4], rm1[4];
#pragma unroll
    for (int mt = 0; mt < 4; mt++) { rm0[mt] = -FLT_MAX; rm1[mt] = -FLT_MAX; }

#define PREFETCH_GRP(gg, st) do {                                            \
        _Pragma("unroll")                                                    \
        for (int it = 0; it < 4; it++) {                                     \
            int rr = 2*it + hi4;                                             \
            int mm = (gg)*8 + rr;                                            \
            int jj = (mm < 32) ? __shfl_sync(0xffffffffu, nA, mm)            \
                   : (mm < Kn) ? __shfl_sync(0xffffffffu, nB, mm - 32)       \
                   : i;                                                      \
            cpa16(suBase + (st)*2304 + rr*288 + seg*16,                      \
                  (const char*)g_u + (size_t)jj*256 + seg*16);               \
        }                                                                    \
        asm volatile("cp.async.commit_group;" ::: "memory");                 \
    } while (0)

    PREFETCH_GRP(0, 0);

    for (int g = 0; g < 8; g++) {                     // 8 groups of 8 messages
        if (g < 7) {
            PREFETCH_GRP(g+1, (g+1)&1);
            asm volatile("cp.async.wait_group 1;" ::: "memory");
        } else {
            asm volatile("cp.async.wait_group 0;" ::: "memory");
        }
        __syncwarp();

        const float* su = &sU[warp][g & 1][0][0];
        uint32_t bH[4][2], bL[4][2];
#pragma unroll
        for (int kt = 0; kt < 4; kt++) {
            float2 uA = *(const float2*)(su + mrow*72 + kt*16 + cb);
            float2 uB = *(const float2*)(su + mrow*72 + kt*16 + cb + 8);
            float h0 = fmaxf(uA.x - vA[kt].x, 0.f);
            float h1 = fmaxf(uA.y - vA[kt].y, 0.f);
            float h2 = fmaxf(uB.x - vB[kt].x, 0.f);
            float h3 = fmaxf(uB.y - vB[kt].y, 0.f);
            __half q0 = __float2half_rn(h0), q1 = __float2half_rn(h1);
            __half q2 = __float2half_rn(h2), q3 = __float2half_rn(h3);
            bH[kt][0] = pkh2(q0, q1);
            bH[kt][1] = pkh2(q2, q3);
            bL[kt][0] = pkh2(__float2half_rn(h0 - __half2float(q0)),
                             __float2half_rn(h1 - __half2float(q1)));
            bL[kt][1] = pkh2(__float2half_rn(h2 - __half2float(q2)),
                             __float2half_rn(h3 - __half2float(q3)));
        }

#pragma unroll
        for (int mt = 0; mt < 4; mt++) {
            float dh[4] = {0,0,0,0}, dl[4] = {0,0,0,0};
#pragma unroll
            for (int kt = 0; kt < 4; kt++) {
                mma16816(dh, aH[mt][kt], bH[kt]);
                mma16816(dl, aH[mt][kt], bL[kt]);
            }
            float d0 = dh[0] + dl[0];
            float d1 = dh[1] + dl[1];
            float d2 = dh[2] + dl[2];
            float d3 = dh[3] + dl[3];
            rm0[mt] = fmaxf(rm0[mt], fmaxf(d0, d1));
            rm1[mt] = fmaxf(rm1[mt], fmaxf(d2, d3));
        }
        __syncwarp();   // reads of this stage done before next prefetch lands
    }

#pragma unroll
    for (int mt = 0; mt < 4; mt++) {
        rm0[mt] = fmaxf(rm0[mt], __shfl_xor_sync(0xffffffffu, rm0[mt], 1));
        rm0[mt] = fmaxf(rm0[mt], __shfl_xor_sync(0xffffffffu, rm0[mt], 2));
        rm1[mt] = fmaxf(rm1[mt], __shfl_xor_sync(0xffffffffu, rm1[mt], 1));
        rm1[mt] = fmaxf(rm1[mt], __shfl_xor_sync(0xffffffffu, rm1[mt], 2));
    }
    if ((lane & 3) == 0) {
        int rr = lane >> 2;
#pragma unroll
        for (int mt = 0; mt < 4; mt++) {
            int ch = mt*16 + rr;
            out[(size_t)i*64 + ch]     = fmaxf(rm0[mt] + b2[ch],     0.f);
            out[(size_t)i*64 + ch + 8] = fmaxf(rm1[mt] + b2[ch + 8], 0.f);
        }
    }
}

// ---------------- launcher ----------------------------------------
extern "C" void kernel_launch(void* const* d_in, const int* in_sizes, int n_in,
                              void* d_out, int out_size) {
    const float* x   = (const float*)d_in[0];
    const float* pos = (const float*)d_in[1];
    // d_in[2] = batch (int32) — recomputed analytically
    const float* W1  = (const float*)d_in[3];
    const float* b1  = (const float*)d_in[4];
    const float* W2  = (const float*)d_in[5];
    const float* b2  = (const float*)d_in[6];
    float* out = (float*)d_out;

    long long off_pos   = (long long)Nn * Hd;
    long long off_batch = off_pos + (long long)Nn * 3;
    long long off_edge  = off_batch + Nn;
    long long need      = off_edge + 2LL * En;
    int write_aux = ((long long)out_size >= need) ? 1 : 0;

    knn_kernel<<<Bev*8, 64>>>(pos, x, W1, b1, out, write_aux, off_pos, off_batch, off_edge);
    mlp3_kernel<<<Nn / 4, 128>>>(W2, b2, out);
}

// round 14
// speedup vs baseline: 1.6086x; 1.2904x over previous
#include <cuda_runtime.h>
#include <cuda_fp16.h>
#include <cstdint>
#include <cfloat>
#include <math_constants.h>

#define Bev 128
#define Pn  200
#define Kn  60
#define Hd  64
#define Nn  (Bev*Pn)          // 25600
#define En  (Nn*Kn)           // 1,536,000

// ---------------- scratch (no cudaMalloc allowed) ----------------
__device__ __align__(16) float g_u[Nn*Hd];   // u = x@W1[:4] + pos@W1[4:] + b1
__device__ __align__(16) float g_v[Nn*Hd];   // v = pos@W1[4:]
__device__ int   g_nbr[En];                  // sorted knn neighbor ids

// ================= helpers =========================================
__device__ __forceinline__ uint32_t smem_u32(const void* p) {
    uint32_t a;
    asm("{ .reg .u64 t; cvta.to.shared.u64 t, %1; cvt.u32.u64 %0, t; }" : "=r"(a) : "l"(p));
    return a;
}
__device__ __forceinline__ void ldsm4(uint32_t* r, uint32_t addr) {
    asm volatile("ldmatrix.sync.aligned.m8n8.x4.shared.b16 {%0,%1,%2,%3}, [%4];"
        : "=r"(r[0]), "=r"(r[1]), "=r"(r[2]), "=r"(r[3]) : "r"(addr));
}
__device__ __forceinline__ void mma16816(float* d, const uint32_t* a, const uint32_t* b) {
    asm volatile("mma.sync.aligned.m16n8k16.row.col.f32.f16.f16.f32 "
        "{%0,%1,%2,%3}, {%4,%5,%6,%7}, {%8,%9}, {%0,%1,%2,%3};"
        : "+f"(d[0]), "+f"(d[1]), "+f"(d[2]), "+f"(d[3])
        : "r"(a[0]), "r"(a[1]), "r"(a[2]), "r"(a[3]), "r"(b[0]), "r"(b[1]));
}
__device__ __forceinline__ uint32_t pkh2(__half a, __half b) {
    __half2 t = __halves2half2(a, b);
    return *reinterpret_cast<uint32_t*>(&t);
}
__device__ __forceinline__ void cpa16(uint32_t dst, const void* src) {
    asm volatile("cp.async.cg.shared.global [%0], [%1], 16;" :: "r"(dst), "l"(src));
}

// ------- kernel 1: fused uv + warp-bitonic exact knn (sorted top-60) -----
// One warp per target. u64 keys (d2bits<<32 | j): single compare == stable
// (d2 asc, j asc), identical tie semantics to lax.top_k and the R1-R3
// passing kernels. Full 256-element bitonic sort (8 elems/lane, 36 phases,
// all unrolled, branch-free) -> top-60 read off elements 0..59.
__global__ void __launch_bounds__(256, 1)
knn_kernel(const float* __restrict__ pos, const float* __restrict__ x,
           const float* __restrict__ W1, const float* __restrict__ b1,
           float* __restrict__ out,
           int write_aux, long long off_pos, long long off_batch, long long off_edge) {
    __shared__ float spx[Pn], spy[Pn], spz[Pn];
    __shared__ float sW1[7*64];
    __shared__ float sb1[64];
    int blk = blockIdx.x;              // 0..3199
    int b   = blk / 25;                // event
    int q   = blk % 25;                // 8-target group
    int tid = threadIdx.x, lane = tid & 31, warp = tid >> 5;

    for (int t = tid; t < Pn; t += 256) {
        spx[t] = pos[(b*Pn+t)*3+0];
        spy[t] = pos[(b*Pn+t)*3+1];
        spz[t] = pos[(b*Pn+t)*3+2];
    }
    for (int t = tid; t < 7*64; t += 256) sW1[t] = W1[t];
    if (tid < 64) sb1[tid] = b1[tid];
    __syncthreads();

    // ---- uv for this block's 8 nodes (512 outputs, 2/thread) ----
    for (int e = tid; e < 8*64; e += 256) {
        int nl = e >> 6, c = e & 63;
        int n  = q*8 + nl;
        int gn = b*Pn + n;
        float4 xv = *(const float4*)(x + (size_t)gn*4);
        float a = sb1[c];
        a = fmaf(xv.x, sW1[0*64+c], a);
        a = fmaf(xv.y, sW1[1*64+c], a);
        a = fmaf(xv.z, sW1[2*64+c], a);
        a = fmaf(xv.w, sW1[3*64+c], a);
        float vv = spx[n] * sW1[4*64+c];
        vv = fmaf(spy[n], sW1[5*64+c], vv);
        vv = fmaf(spz[n], sW1[6*64+c], vv);
        g_u[(size_t)gn*64 + c] = a + vv;
        g_v[(size_t)gn*64 + c] = vv;
    }

    // ---- knn: one warp per target, bitonic sort of 256 u64 keys ----
    int i  = q*8 + warp;
    int gi = b*Pn + i;
    float pix = spx[i], piy = spy[i], piz = spz[i];

    unsigned long long v[8];
#pragma unroll
    for (int r = 0; r < 7; r++) {
        int j  = r*32 + lane;
        int js = (j < Pn) ? j : 0;
        float dx = spx[js]-pix, dy = spy[js]-piy, dz = spz[js]-piz;
        float d2 = dx*dx; d2 = fmaf(dy,dy,d2); d2 = fmaf(dz,dz,d2);
        bool valid = (j < Pn) && (j != i);
        v[r] = valid ? (((unsigned long long)__float_as_uint(d2) << 32) | (unsigned)j)
                     : ~0ull;
    }
    v[7] = ~0ull;

    // bitonic ascending sort, element index e = r*32 + lane
#pragma unroll
    for (int k = 2; k <= 256; k <<= 1) {
#pragma unroll
        for (int s = 128; s > 0; s >>= 1) {
            if (s >= k) continue;
            if (s < 32) {
#pragma unroll
                for (int r = 0; r < 8; r++) {
                    unsigned long long o = __shfl_xor_sync(0xffffffffu, v[r], s);
                    bool lower = (lane & s) == 0;
                    bool up    = (((r*32 + lane) & k) == 0);
                    unsigned long long mn = (v[r] < o) ? v[r] : o;
                    unsigned long long mx = (v[r] < o) ? o : v[r];
                    v[r] = (lower == up) ? mn : mx;
                }
            } else {
                int sr = s >> 5;
#pragma unroll
                for (int r = 0; r < 8; r++) {
                    int pr = r ^ sr;
                    if (pr > r) {
                        bool up = (((r*32) & k) == 0);
                        unsigned long long a  = v[r], bb = v[pr];
                        bool sw = (a > bb) == up;
                        v[r]  = sw ? bb : a;
                        v[pr] = sw ? a : bb;
                    }
                }
            }
        }
    }

    // top-60 = elements 0..59: v[0] (t=lane), v[1] (t=32+lane, lane<28)
    {
        int j0 = (int)(v[0] & 0xffffffffull);
        g_nbr[(size_t)gi*Kn + lane] = b*Pn + j0;
        if (write_aux) {
            out[off_edge +      (long long)gi*Kn + lane] = (float)(b*Pn + j0);
            out[off_edge + En + (long long)gi*Kn + lane] = (float)gi;
        }
        if (lane < Kn - 32) {
            int j1 = (int)(v[1] & 0xffffffffull);
            g_nbr[(size_t)gi*Kn + 32 + lane] = b*Pn + j1;
            if (write_aux) {
                out[off_edge +      (long long)gi*Kn + 32 + lane] = (float)(b*Pn + j1);
                out[off_edge + En + (long long)gi*Kn + 32 + lane] = (float)gi;
            }
        }
        if (lane == 0 && write_aux) {
            out[off_pos + (long long)gi*3+0] = pix;
            out[off_pos + (long long)gi*3+1] = piy;
            out[off_pos + (long long)gi*3+2] = piz;
            out[off_batch + gi] = (float)b;
        }
    }
}

// ---------------- kernel 2: HMMA mlp + fused max-aggregate --------
// (byte-exact round-13 version — known good at 103.5us, rel_err 1.3e-4)
__global__ void __launch_bounds__(128)
mlp3_kernel(const float* __restrict__ W2, const float* __restrict__ b2,
            float* __restrict__ out) {
    __shared__ __align__(16) __half sW[64][72];       // W2^T hi only
    __shared__ __align__(16) float  sU[4][2][8][72];  // [warp][stage][row][64+pad]
    int tid = threadIdx.x, lane = tid & 31, warp = tid >> 5;

    for (int e = tid; e < 64*64; e += 128) {
        int k = e >> 6, ch = e & 63;
        sW[ch][k] = __float2half_rn(W2[k*64 + ch]);
    }
    __syncthreads();

    const int r = (lane & 7) + ((lane >> 3) & 1) * 8;
    const int c = ((lane >> 4) & 1) * 8;

    uint32_t aH[4][4][4];
#pragma unroll
    for (int mt = 0; mt < 4; mt++)
#pragma unroll
        for (int kt = 0; kt < 4; kt++)
            ldsm4(aH[mt][kt], smem_u32(&sW[mt*16 + r][kt*16 + c]));

    int i = blockIdx.x * 4 + warp;                    // node id
    const int cb = (lane & 3) * 2;                    // k base within k-tile
    const int mrow = lane >> 2;                       // message row in group
    const int seg  = lane & 15;                       // 16B chunk within row
    const int hi4  = lane >> 4;                       // row parity for prefetch

    int nA = g_nbr[(size_t)i*Kn + lane];
    int nB = (lane < Kn - 32) ? g_nbr[(size_t)i*Kn + 32 + lane] : 0;

    const uint32_t suBase = smem_u32(&sU[warp][0][0][0]);   // stage stride 2304B

    float2 vA[4], vB[4];
#pragma unroll
    for (int kt = 0; kt < 4; kt++) {
        vA[kt] = *(const float2*)(g_v + (size_t)i*64 + kt*16 + cb);
        vB[kt] = *(const float2*)(g_v + (size_t)i*64 + kt*16 + cb + 8);
    }

    float rm0[4], rm1[4];
#pragma unroll
    for (int mt = 0; mt < 4; mt++) { rm0[mt] = -FLT_MAX; rm1[mt] = -FLT_MAX; }

#define PREFETCH_GRP(gg, st) do {                                            \
        _Pragma("unroll")                                                    \
        for (int it = 0; it < 4; it++) {                                     \
            int rr = 2*it + hi4;                                             \
            int mm = (gg)*8 + rr;                                            \
            int jj = (mm < 32) ? __shfl_sync(0xffffffffu, nA, mm)            \
                   : (mm < Kn) ? __shfl_sync(0xffffffffu, nB, mm - 32)       \
                   : i;                                                      \
            cpa16(suBase + (st)*2304 + rr*288 + seg*16,                      \
                  (const char*)g_u + (size_t)jj*256 + seg*16);               \
        }                                                                    \
        asm volatile("cp.async.commit_group;" ::: "memory");                 \
    } while (0)

    PREFETCH_GRP(0, 0);

    for (int g = 0; g < 8; g++) {                     // 8 groups of 8 messages
        if (g < 7) {
            PREFETCH_GRP(g+1, (g+1)&1);
            asm volatile("cp.async.wait_group 1;" ::: "memory");
        } else {
            asm volatile("cp.async.wait_group 0;" ::: "memory");
        }
        __syncwarp();

        const float* su = &sU[warp][g & 1][0][0];
        uint32_t bH[4][2], bL[4][2];
#pragma unroll
        for (int kt = 0; kt < 4; kt++) {
            float2 uA = *(const float2*)(su + mrow*72 + kt*16 + cb);
            float2 uB = *(const float2*)(su + mrow*72 + kt*16 + cb + 8);
            float h0 = fmaxf(uA.x - vA[kt].x, 0.f);
            float h1 = fmaxf(uA.y - vA[kt].y, 0.f);
            float h2 = fmaxf(uB.x - vB[kt].x, 0.f);
            float h3 = fmaxf(uB.y - vB[kt].y, 0.f);
            __half q0 = __float2half_rn(h0), q1 = __float2half_rn(h1);
            __half q2 = __float2half_rn(h2), q3 = __float2half_rn(h3);
            bH[kt][0] = pkh2(q0, q1);
            bH[kt][1] = pkh2(q2, q3);
            bL[kt][0] = pkh2(__float2half_rn(h0 - __half2float(q0)),
                             __float2half_rn(h1 - __half2float(q1)));
            bL[kt][1] = pkh2(__float2half_rn(h2 - __half2float(q2)),
                             __float2half_rn(h3 - __half2float(q3)));
        }

#pragma unroll
        for (int mt = 0; mt < 4; mt++) {
            float dh[4] = {0,0,0,0}, dl[4] = {0,0,0,0};
#pragma unroll
            for (int kt = 0; kt < 4; kt++) {
                mma16816(dh, aH[mt][kt], bH[kt]);
                mma16816(dl, aH[mt][kt], bL[kt]);
            }
            float d0 = dh[0] + dl[0];
            float d1 = dh[1] + dl[1];
            float d2 = dh[2] + dl[2];
            float d3 = dh[3] + dl[3];
            rm0[mt] = fmaxf(rm0[mt], fmaxf(d0, d1));
            rm1[mt] = fmaxf(rm1[mt], fmaxf(d2, d3));
        }
        __syncwarp();   // reads of this stage done before next prefetch lands
    }

#pragma unroll
    for (int mt = 0; mt < 4; mt++) {
        rm0[mt] = fmaxf(rm0[mt], __shfl_xor_sync(0xffffffffu, rm0[mt], 1));
        rm0[mt] = fmaxf(rm0[mt], __shfl_xor_sync(0xffffffffu, rm0[mt], 2));
        rm1[mt] = fmaxf(rm1[mt], __shfl_xor_sync(0xffffffffu, rm1[mt], 1));
        rm1[mt] = fmaxf(rm1[mt], __shfl_xor_sync(0xffffffffu, rm1[mt], 2));
    }
    if ((lane & 3) == 0) {
        int rr = lane >> 2;
#pragma unroll
        for (int mt = 0; mt < 4; mt++) {
            int ch = mt*16 + rr;
            out[(size_t)i*64 + ch]     = fmaxf(rm0[mt] + b2[ch],     0.f);
            out[(size_t)i*64 + ch + 8] = fmaxf(rm1[mt] + b2[ch + 8], 0.f);
        }
    }
}

// ---------------- launcher ----------------------------------------
extern "C" void kernel_launch(void* const* d_in, const int* in_sizes, int n_in,
                              void* d_out, int out_size) {
    const float* x   = (const float*)d_in[0];
    const float* pos = (const float*)d_in[1];
    // d_in[2] = batch (int32) — recomputed analytically
    const float* W1  = (const float*)d_in[3];
    const float* b1  = (const float*)d_in[4];
    const float* W2  = (const float*)d_in[5];
    const float* b2  = (const float*)d_in[6];
    float* out = (float*)d_out;

    long long off_pos   = (long long)Nn * Hd;
    long long off_batch = off_pos + (long long)Nn * 3;
    long long off_edge  = off_batch + Nn;
    long long need      = off_edge + 2LL * En;
    int write_aux = ((long long)out_size >= need) ? 1 : 0;

    knn_kernel<<<Bev*25, 256>>>(pos, x, W1, b1, out, write_aux, off_pos, off_batch, off_edge);
    mlp3_kernel<<<Nn / 4, 128>>>(W2, b2, out);
}

// round 15
// speedup vs baseline: 1.8223x; 1.1329x over previous
#include <cuda_runtime.h>
#include <cuda_fp16.h>
#include <cstdint>
#include <cfloat>
#include <math_constants.h>

#define Bev 128
#define Pn  200
#define Kn  60
#define Hd  64
#define Nn  (Bev*Pn)          // 25600
#define En  (Nn*Kn)           // 1,536,000

// ---------------- scratch (no cudaMalloc allowed) ----------------
__device__ __align__(16) float g_u[Nn*Hd];   // u = x@W1[:4] + pos@W1[4:] + b1
__device__ __align__(16) float g_v[Nn*Hd];   // v = pos@W1[4:]
__device__ int   g_nbr[En];                  // sorted knn neighbor ids

// ================= helpers =========================================
__device__ __forceinline__ uint32_t smem_u32(const void* p) {
    uint32_t a;
    asm("{ .reg .u64 t; cvta.to.shared.u64 t, %1; cvt.u32.u64 %0, t; }" : "=r"(a) : "l"(p));
    return a;
}
__device__ __forceinline__ void ldsm4(uint32_t* r, uint32_t addr) {
    asm volatile("ldmatrix.sync.aligned.m8n8.x4.shared.b16 {%0,%1,%2,%3}, [%4];"
        : "=r"(r[0]), "=r"(r[1]), "=r"(r[2]), "=r"(r[3]) : "r"(addr));
}
__device__ __forceinline__ void mma16816(float* d, const uint32_t* a, const uint32_t* b) {
    asm volatile("mma.sync.aligned.m16n8k16.row.col.f32.f16.f16.f32 "
        "{%0,%1,%2,%3}, {%4,%5,%6,%7}, {%8,%9}, {%0,%1,%2,%3};"
        : "+f"(d[0]), "+f"(d[1]), "+f"(d[2]), "+f"(d[3])
        : "r"(a[0]), "r"(a[1]), "r"(a[2]), "r"(a[3]), "r"(b[0]), "r"(b[1]));
}
__device__ __forceinline__ uint32_t pkh2(__half a, __half b) {
    __half2 t = __halves2half2(a, b);
    return *reinterpret_cast<uint32_t*>(&t);
}
__device__ __forceinline__ void cpa16(uint32_t dst, const void* src) {
    asm volatile("cp.async.cg.shared.global [%0], [%1], 16;" :: "r"(dst), "l"(src));
}

// ------- kernel 1: fused uv + warp-bitonic exact knn (sorted top-60) -----
// (byte-exact round-14 version — known good, ~80us)
__global__ void __launch_bounds__(256, 1)
knn_kernel(const float* __restrict__ pos, const float* __restrict__ x,
           const float* __restrict__ W1, const float* __restrict__ b1,
           float* __restrict__ out,
           int write_aux, long long off_pos, long long off_batch, long long off_edge) {
    __shared__ float spx[Pn], spy[Pn], spz[Pn];
    __shared__ float sW1[7*64];
    __shared__ float sb1[64];
    int blk = blockIdx.x;              // 0..3199
    int b   = blk / 25;                // event
    int q   = blk % 25;                // 8-target group
    int tid = threadIdx.x, lane = tid & 31, warp = tid >> 5;

    for (int t = tid; t < Pn; t += 256) {
        spx[t] = pos[(b*Pn+t)*3+0];
        spy[t] = pos[(b*Pn+t)*3+1];
        spz[t] = pos[(b*Pn+t)*3+2];
    }
    for (int t = tid; t < 7*64; t += 256) sW1[t] = W1[t];
    if (tid < 64) sb1[tid] = b1[tid];
    __syncthreads();

    // ---- uv for this block's 8 nodes (512 outputs, 2/thread) ----
    for (int e = tid; e < 8*64; e += 256) {
        int nl = e >> 6, c = e & 63;
        int n  = q*8 + nl;
        int gn = b*Pn + n;
        float4 xv = *(const float4*)(x + (size_t)gn*4);
        float a = sb1[c];
        a = fmaf(xv.x, sW1[0*64+c], a);
        a = fmaf(xv.y, sW1[1*64+c], a);
        a = fmaf(xv.z, sW1[2*64+c], a);
        a = fmaf(xv.w, sW1[3*64+c], a);
        float vv = spx[n] * sW1[4*64+c];
        vv = fmaf(spy[n], sW1[5*64+c], vv);
        vv = fmaf(spz[n], sW1[6*64+c], vv);
        g_u[(size_t)gn*64 + c] = a + vv;
        g_v[(size_t)gn*64 + c] = vv;
    }

    // ---- knn: one warp per target, bitonic sort of 256 u64 keys ----
    int i  = q*8 + warp;
    int gi = b*Pn + i;
    float pix = spx[i], piy = spy[i], piz = spz[i];

    unsigned long long v[8];
#pragma unroll
    for (int r = 0; r < 7; r++) {
        int j  = r*32 + lane;
        int js = (j < Pn) ? j : 0;
        float dx = spx[js]-pix, dy = spy[js]-piy, dz = spz[js]-piz;
        float d2 = dx*dx; d2 = fmaf(dy,dy,d2); d2 = fmaf(dz,dz,d2);
        bool valid = (j < Pn) && (j != i);
        v[r] = valid ? (((unsigned long long)__float_as_uint(d2) << 32) | (unsigned)j)
                     : ~0ull;
    }
    v[7] = ~0ull;

    // bitonic ascending sort, element index e = r*32 + lane
#pragma unroll
    for (int k = 2; k <= 256; k <<= 1) {
#pragma unroll
        for (int s = 128; s > 0; s >>= 1) {
            if (s >= k) continue;
            if (s < 32) {
#pragma unroll
                for (int r = 0; r < 8; r++) {
                    unsigned long long o = __shfl_xor_sync(0xffffffffu, v[r], s);
                    bool lower = (lane & s) == 0;
                    bool up    = (((r*32 + lane) & k) == 0);
                    unsigned long long mn = (v[r] < o) ? v[r] : o;
                    unsigned long long mx = (v[r] < o) ? o : v[r];
                    v[r] = (lower == up) ? mn : mx;
                }
            } else {
                int sr = s >> 5;
#pragma unroll
                for (int r = 0; r < 8; r++) {
                    int pr = r ^ sr;
                    if (pr > r) {
                        bool up = (((r*32) & k) == 0);
                        unsigned long long a  = v[r], bb = v[pr];
                        bool sw = (a > bb) == up;
                        v[r]  = sw ? bb : a;
                        v[pr] = sw ? a : bb;
                    }
                }
            }
        }
    }

    // top-60 = elements 0..59: v[0] (t=lane), v[1] (t=32+lane, lane<28)
    {
        int j0 = (int)(v[0] & 0xffffffffull);
        g_nbr[(size_t)gi*Kn + lane] = b*Pn + j0;
        if (write_aux) {
            out[off_edge +      (long long)gi*Kn + lane] = (float)(b*Pn + j0);
            out[off_edge + En + (long long)gi*Kn + lane] = (float)gi;
        }
        if (lane < Kn - 32) {
            int j1 = (int)(v[1] & 0xffffffffull);
            g_nbr[(size_t)gi*Kn + 32 + lane] = b*Pn + j1;
            if (write_aux) {
                out[off_edge +      (long long)gi*Kn + 32 + lane] = (float)(b*Pn + j1);
                out[off_edge + En + (long long)gi*Kn + 32 + lane] = (float)gi;
            }
        }
        if (lane == 0 && write_aux) {
            out[off_pos + (long long)gi*3+0] = pix;
            out[off_pos + (long long)gi*3+1] = piy;
            out[off_pos + (long long)gi*3+2] = piz;
            out[off_batch + gi] = (float)b;
        }
    }
}

// ---------------- kernel 2: HMMA mlp + fused max-aggregate --------
// 1-term fp16: D = aH * bH (both lo terms dropped). Measured aL-drop error
// was 1.32e-4; bL-drop adds a similar independent term -> ~2e-4 combined,
// 5x under the 1e-3 threshold. MMAs/group 32 -> 16; bL build chain gone.
__global__ void __launch_bounds__(128)
mlp3_kernel(const float* __restrict__ W2, const float* __restrict__ b2,
            float* __restrict__ out) {
    __shared__ __align__(16) __half sW[64][72];       // W2^T hi only
    __shared__ __align__(16) float  sU[4][2][8][72];  // [warp][stage][row][64+pad]
    int tid = threadIdx.x, lane = tid & 31, warp = tid >> 5;

    for (int e = tid; e < 64*64; e += 128) {
        int k = e >> 6, ch = e & 63;
        sW[ch][k] = __float2half_rn(W2[k*64 + ch]);
    }
    __syncthreads();

    const int r = (lane & 7) + ((lane >> 3) & 1) * 8;
    const int c = ((lane >> 4) & 1) * 8;

    uint32_t aH[4][4][4];
#pragma unroll
    for (int mt = 0; mt < 4; mt++)
#pragma unroll
        for (int kt = 0; kt < 4; kt++)
            ldsm4(aH[mt][kt], smem_u32(&sW[mt*16 + r][kt*16 + c]));

    int i = blockIdx.x * 4 + warp;                    // node id
    const int cb = (lane & 3) * 2;                    // k base within k-tile
    const int mrow = lane >> 2;                       // message row in group
    const int seg  = lane & 15;                       // 16B chunk within row
    const int hi4  = lane >> 4;                       // row parity for prefetch

    int nA = g_nbr[(size_t)i*Kn + lane];
    int nB = (lane < Kn - 32) ? g_nbr[(size_t)i*Kn + 32 + lane] : 0;

    const uint32_t suBase = smem_u32(&sU[warp][0][0][0]);   // stage stride 2304B

    float2 vA[4], vB[4];
#pragma unroll
    for (int kt = 0; kt < 4; kt++) {
        vA[kt] = *(const float2*)(g_v + (size_t)i*64 + kt*16 + cb);
        vB[kt] = *(const float2*)(g_v + (size_t)i*64 + kt*16 + cb + 8);
    }

    float rm0[4], rm1[4];
#pragma unroll
    for (int mt = 0; mt < 4; mt++) { rm0[mt] = -FLT_MAX; rm1[mt] = -FLT_MAX; }

#define PREFETCH_GRP(gg, st) do {                                            \
        _Pragma("unroll")                                                    \
        for (int it = 0; it < 4; it++) {                                     \
            int rr = 2*it + hi4;                                             \
            int mm = (gg)*8 + rr;                                            \
            int jj = (mm < 32) ? __shfl_sync(0xffffffffu, nA, mm)            \
                   : (mm < Kn) ? __shfl_sync(0xffffffffu, nB, mm - 32)       \
                   : i;                                                      \
            cpa16(suBase + (st)*2304 + rr*288 + seg*16,                      \
                  (const char*)g_u + (size_t)jj*256 + seg*16);               \
        }                                                                    \
        asm volatile("cp.async.commit_group;" ::: "memory");                 \
    } while (0)

    PREFETCH_GRP(0, 0);

    for (int g = 0; g < 8; g++) {                     // 8 groups of 8 messages
        if (g < 7) {
            PREFETCH_GRP(g+1, (g+1)&1);
            asm volatile("cp.async.wait_group 1;" ::: "memory");
        } else {
            asm volatile("cp.async.wait_group 0;" ::: "memory");
        }
        __syncwarp();

        const float* su = &sU[warp][g & 1][0][0];
        uint32_t bH[4][2];
#pragma unroll
        for (int kt = 0; kt < 4; kt++) {
            float2 uA = *(const float2*)(su + mrow*72 + kt*16 + cb);
            float2 uB = *(const float2*)(su + mrow*72 + kt*16 + cb + 8);
            float h0 = fmaxf(uA.x - vA[kt].x, 0.f);
            float h1 = fmaxf(uA.y - vA[kt].y, 0.f);
            float h2 = fmaxf(uB.x - vB[kt].x, 0.f);
            float h3 = fmaxf(uB.y - vB[kt].y, 0.f);
            bH[kt][0] = pkh2(__float2half_rn(h0), __float2half_rn(h1));
            bH[kt][1] = pkh2(__float2half_rn(h2), __float2half_rn(h3));
        }

#pragma unroll
        for (int mt = 0; mt < 4; mt++) {
            float dh[4] = {0,0,0,0};
#pragma unroll
            for (int kt = 0; kt < 4; kt++)
                mma16816(dh, aH[mt][kt], bH[kt]);
            rm0[mt] = fmaxf(rm0[mt], fmaxf(dh[0], dh[1]));
            rm1[mt] = fmaxf(rm1[mt], fmaxf(dh[2], dh[3]));
        }
        __syncwarp();   // reads of this stage done before next prefetch lands
    }

#pragma unroll
    for (int mt = 0; mt < 4; mt++) {
        rm0[mt] = fmaxf(rm0[mt], __shfl_xor_sync(0xffffffffu, rm0[mt], 1));
        rm0[mt] = fmaxf(rm0[mt], __shfl_xor_sync(0xffffffffu, rm0[mt], 2));
        rm1[mt] = fmaxf(rm1[mt], __shfl_xor_sync(0xffffffffu, rm1[mt], 1));
        rm1[mt] = fmaxf(rm1[mt], __shfl_xor_sync(0xffffffffu, rm1[mt], 2));
    }
    if ((lane & 3) == 0) {
        int rr = lane >> 2;
#pragma unroll
        for (int mt = 0; mt < 4; mt++) {
            int ch = mt*16 + rr;
            out[(size_t)i*64 + ch]     = fmaxf(rm0[mt] + b2[ch],     0.f);
            out[(size_t)i*64 + ch + 8] = fmaxf(rm1[mt] + b2[ch + 8], 0.f);
        }
    }
}

// ---------------- launcher ----------------------------------------
extern "C" void kernel_launch(void* const* d_in, const int* in_sizes, int n_in,
                              void* d_out, int out_size) {
    const float* x   = (const float*)d_in[0];
    const float* pos = (const float*)d_in[1];
    // d_in[2] = batch (int32) — recomputed analytically
    const float* W1  = (const float*)d_in[3];
    const float* b1  = (const float*)d_in[4];
    const float* W2  = (const float*)d_in[5];
    const float* b2  = (const float*)d_in[6];
    float* out = (float*)d_out;

    long long off_pos   = (long long)Nn * Hd;
    long long off_batch = off_pos + (long long)Nn * 3;
    long long off_edge  = off_batch + Nn;
    long long need      = off_edge + 2LL * En;
    int write_aux = ((long long)out_size >= need) ? 1 : 0;

    knn_kernel<<<Bev*25, 256>>>(pos, x, W1, b1, out, write_aux, off_pos, off_batch, off_edge);
    mlp3_kernel<<<Nn / 4, 128>>>(W2, b2, out);
}

// round 16
// speedup vs baseline: 2.0496x; 1.1247x over previous
#include <cuda_runtime.h>
#include <cuda_fp16.h>
#include <cstdint>
#include <cfloat>
#include <math_constants.h>

#define Bev 128
#define Pn  200
#define Kn  60
#define Hd  64
#define Nn  (Bev*Pn)          // 25600
#define En  (Nn*Kn)           // 1,536,000

// ---------------- scratch (no cudaMalloc allowed) ----------------
__device__ __align__(16) __half g_uh[Nn*Hd];  // fp16 u = x@W1[:4]+pos@W1[4:]+b1
__device__ __align__(16) __half g_vh[Nn*Hd];  // fp16 v = pos@W1[4:]
__device__ int g_nbr[En];                     // sorted knn neighbor ids

// ================= helpers =========================================
__device__ __forceinline__ uint32_t smem_u32(const void* p) {
    uint32_t a;
    asm("{ .reg .u64 t; cvta.to.shared.u64 t, %1; cvt.u32.u64 %0, t; }" : "=r"(a) : "l"(p));
    return a;
}
__device__ __forceinline__ void ldsm4(uint32_t* r, uint32_t addr) {
    asm volatile("ldmatrix.sync.aligned.m8n8.x4.shared.b16 {%0,%1,%2,%3}, [%4];"
        : "=r"(r[0]), "=r"(r[1]), "=r"(r[2]), "=r"(r[3]) : "r"(addr));
}
__device__ __forceinline__ void mma16816(float* d, const uint32_t* a, const uint32_t* b) {
    asm volatile("mma.sync.aligned.m16n8k16.row.col.f32.f16.f16.f32 "
        "{%0,%1,%2,%3}, {%4,%5,%6,%7}, {%8,%9}, {%0,%1,%2,%3};"
        : "+f"(d[0]), "+f"(d[1]), "+f"(d[2]), "+f"(d[3])
        : "r"(a[0]), "r"(a[1]), "r"(a[2]), "r"(a[3]), "r"(b[0]), "r"(b[1]));
}
__device__ __forceinline__ void cpa16(uint32_t dst, const void* src) {
    asm volatile("cp.async.cg.shared.global [%0], [%1], 16;" :: "r"(dst), "l"(src));
}
__device__ __forceinline__ uint32_t h2bits(__half2 h) {
    return *reinterpret_cast<uint32_t*>(&h);
}

// ------- kernel 1: fused uv + warp-bitonic exact knn (sorted top-60) -----
// (round-14 version; only the uv STORES changed to fp16 — selection logic
//  byte-identical)
__global__ void __launch_bounds__(256, 1)
knn_kernel(const float* __restrict__ pos, const float* __restrict__ x,
           const float* __restrict__ W1, const float* __restrict__ b1,
           float* __restrict__ out,
           int write_aux, long long off_pos, long long off_batch, long long off_edge) {
    __shared__ float spx[Pn], spy[Pn], spz[Pn];
    __shared__ float sW1[7*64];
    __shared__ float sb1[64];
    int blk = blockIdx.x;              // 0..3199
    int b   = blk / 25;                // event
    int q   = blk % 25;                // 8-target group
    int tid = threadIdx.x, lane = tid & 31, warp = tid >> 5;

    for (int t = tid; t < Pn; t += 256) {
        spx[t] = pos[(b*Pn+t)*3+0];
        spy[t] = pos[(b*Pn+t)*3+1];
        spz[t] = pos[(b*Pn+t)*3+2];
    }
    for (int t = tid; t < 7*64; t += 256) sW1[t] = W1[t];
    if (tid < 64) sb1[tid] = b1[tid];
    __syncthreads();

    // ---- uv for this block's 8 nodes (fp16 stores) ----
    for (int e = tid; e < 8*64; e += 256) {
        int nl = e >> 6, c = e & 63;
        int n  = q*8 + nl;
        int gn = b*Pn + n;
        float4 xv = *(const float4*)(x + (size_t)gn*4);
        float a = sb1[c];
        a = fmaf(xv.x, sW1[0*64+c], a);
        a = fmaf(xv.y, sW1[1*64+c], a);
        a = fmaf(xv.z, sW1[2*64+c], a);
        a = fmaf(xv.w, sW1[3*64+c], a);
        float vv = spx[n] * sW1[4*64+c];
        vv = fmaf(spy[n], sW1[5*64+c], vv);
        vv = fmaf(spz[n], sW1[6*64+c], vv);
        g_uh[(size_t)gn*64 + c] = __float2half_rn(a + vv);
        g_vh[(size_t)gn*64 + c] = __float2half_rn(vv);
    }

    // ---- knn: one warp per target, bitonic sort of 256 u64 keys ----
    int i  = q*8 + warp;
    int gi = b*Pn + i;
    float pix = spx[i], piy = spy[i], piz = spz[i];

    unsigned long long v[8];
#pragma unroll
    for (int r = 0; r < 7; r++) {
        int j  = r*32 + lane;
        int js = (j < Pn) ? j : 0;
        float dx = spx[js]-pix, dy = spy[js]-piy, dz = spz[js]-piz;
        float d2 = dx*dx; d2 = fmaf(dy,dy,d2); d2 = fmaf(dz,dz,d2);
        bool valid = (j < Pn) && (j != i);
        v[r] = valid ? (((unsigned long long)__float_as_uint(d2) << 32) | (unsigned)j)
                     : ~0ull;
    }
    v[7] = ~0ull;

#pragma unroll
    for (int k = 2; k <= 256; k <<= 1) {
#pragma unroll
        for (int s = 128; s > 0; s >>= 1) {
            if (s >= k) continue;
            if (s < 32) {
#pragma unroll
                for (int r = 0; r < 8; r++) {
                    unsigned long long o = __shfl_xor_sync(0xffffffffu, v[r], s);
                    bool lower = (lane & s) == 0;
                    bool up    = (((r*32 + lane) & k) == 0);
                    unsigned long long mn = (v[r] < o) ? v[r] : o;
                    unsigned long long mx = (v[r] < o) ? o : v[r];
                    v[r] = (lower == up) ? mn : mx;
                }
            } else {
                int sr = s >> 5;
#pragma unroll
                for (int r = 0; r < 8; r++) {
                    int pr = r ^ sr;
                    if (pr > r) {
                        bool up = (((r*32) & k) == 0);
                        unsigned long long a  = v[r], bb = v[pr];
                        bool sw = (a > bb) == up;
                        v[r]  = sw ? bb : a;
                        v[pr] = sw ? a : bb;
                    }
                }
            }
        }
    }

    {
        int j0 = (int)(v[0] & 0xffffffffull);
        g_nbr[(size_t)gi*Kn + lane] = b*Pn + j0;
        if (write_aux) {
            out[off_edge +      (long long)gi*Kn + lane] = (float)(b*Pn + j0);
            out[off_edge + En + (long long)gi*Kn + lane] = (float)gi;
        }
        if (lane < Kn - 32) {
            int j1 = (int)(v[1] & 0xffffffffull);
            g_nbr[(size_t)gi*Kn + 32 + lane] = b*Pn + j1;
            if (write_aux) {
                out[off_edge +      (long long)gi*Kn + 32 + lane] = (float)(b*Pn + j1);
                out[off_edge + En + (long long)gi*Kn + 32 + lane] = (float)gi;
            }
        }
        if (lane == 0 && write_aux) {
            out[off_pos + (long long)gi*3+0] = pix;
            out[off_pos + (long long)gi*3+1] = piy;
            out[off_pos + (long long)gi*3+2] = piz;
            out[off_batch + gi] = (float)b;
        }
    }
}

// ---------------- kernel 2: HMMA mlp + fused max-aggregate --------
// fp16 u/v: b-build is 2 LDS.32 + HSUB2 + HMAX2 per kt-tile (the fp32
// subtract/cvt/pack chain is gone). Gather rows halve to 128B -> 2 cp.async
// per lane per group. Stage rows stride 88 halves (176B: 16B-aligned,
// conflict-free bank mapping for 8 rows). MMA structure unchanged from R15.
__global__ void __launch_bounds__(128)
mlp3_kernel(const float* __restrict__ W2, const float* __restrict__ b2,
            float* __restrict__ out) {
    __shared__ __align__(16) __half sW[64][72];       // W2^T hi
    __shared__ __align__(16) __half sU[4][2][8][88];  // [warp][stage][row][64+pad]
    int tid = threadIdx.x, lane = tid & 31, warp = tid >> 5;

    for (int e = tid; e < 64*64; e += 128) {
        int k = e >> 6, ch = e & 63;
        sW[ch][k] = __float2half_rn(W2[k*64 + ch]);
    }
    __syncthreads();

    const int r = (lane & 7) + ((lane >> 3) & 1) * 8;
    const int c = ((lane >> 4) & 1) * 8;

    uint32_t aH[4][4][4];
#pragma unroll
    for (int mt = 0; mt < 4; mt++)
#pragma unroll
        for (int kt = 0; kt < 4; kt++)
            ldsm4(aH[mt][kt], smem_u32(&sW[mt*16 + r][kt*16 + c]));

    int i = blockIdx.x * 4 + warp;                    // node id
    const int cb = (lane & 3) * 2;                    // k base within k-tile
    const int mrow = lane >> 2;                       // message row in group
    const int seg  = lane & 7;                        // 16B chunk within 128B row
    const int rq   = lane >> 3;                       // row quarter for prefetch

    int nA = g_nbr[(size_t)i*Kn + lane];
    int nB = (lane < Kn - 32) ? g_nbr[(size_t)i*Kn + 32 + lane] : 0;

    const uint32_t suBase = smem_u32(&sU[warp][0][0][0]);   // stage stride 1408B

    const __half2 hzero = __floats2half2_rn(0.f, 0.f);
    __half2 vA2[4], vB2[4];
#pragma unroll
    for (int kt = 0; kt < 4; kt++) {
        vA2[kt] = *(const __half2*)(g_vh + (size_t)i*64 + kt*16 + cb);
        vB2[kt] = *(const __half2*)(g_vh + (size_t)i*64 + kt*16 + cb + 8);
    }

    float rm0[4], rm1[4];
#pragma unroll
    for (int mt = 0; mt < 4; mt++) { rm0[mt] = -FLT_MAX; rm1[mt] = -FLT_MAX; }

#define PREFETCH_GRP(gg, st) do {                                            \
        _Pragma("unroll")                                                    \
        for (int it = 0; it < 2; it++) {                                     \
            int rr = it*4 + rq;                                              \
            int mm = (gg)*8 + rr;                                            \
            int jj = (mm < 32) ? __shfl_sync(0xffffffffu, nA, mm)            \
                   : (mm < Kn) ? __shfl_sync(0xffffffffu, nB, mm - 32)       \
                   : i;                                                      \
            cpa16(suBase + (st)*1408 + rr*176 + seg*16,                      \
                  (const char*)g_uh + (size_t)jj*128 + seg*16);              \
        }                                                                    \
        asm volatile("cp.async.commit_group;" ::: "memory");                 \
    } while (0)

    PREFETCH_GRP(0, 0);

    for (int g = 0; g < 8; g++) {                     // 8 groups of 8 messages
        if (g < 7) {
            PREFETCH_GRP(g+1, (g+1)&1);
            asm volatile("cp.async.wait_group 1;" ::: "memory");
        } else {
            asm volatile("cp.async.wait_group 0;" ::: "memory");
        }
        __syncwarp();

        const __half* su = &sU[warp][g & 1][0][0];
        uint32_t bH[4][2];
#pragma unroll
        for (int kt = 0; kt < 4; kt++) {
            __half2 ua = *(const __half2*)(su + mrow*88 + kt*16 + cb);
            __half2 ub = *(const __half2*)(su + mrow*88 + kt*16 + cb + 8);
            bH[kt][0] = h2bits(__hmax2(__hsub2(ua, vA2[kt]), hzero));
            bH[kt][1] = h2bits(__hmax2(__hsub2(ub, vB2[kt]), hzero));
        }

#pragma unroll
        for (int mt = 0; mt < 4; mt++) {
            float dh[4] = {0,0,0,0};
#pragma unroll
            for (int kt = 0; kt < 4; kt++)
                mma16816(dh, aH[mt][kt], bH[kt]);
            rm0[mt] = fmaxf(rm0[mt], fmaxf(dh[0], dh[1]));
            rm1[mt] = fmaxf(rm1[mt], fmaxf(dh[2], dh[3]));
        }
        __syncwarp();   // reads of this stage done before next prefetch lands
    }

#pragma unroll
    for (int mt = 0; mt < 4; mt++) {
        rm0[mt] = fmaxf(rm0[mt], __shfl_xor_sync(0xffffffffu, rm0[mt], 1));
        rm0[mt] = fmaxf(rm0[mt], __shfl_xor_sync(0xffffffffu, rm0[mt], 2));
        rm1[mt] = fmaxf(rm1[mt], __shfl_xor_sync(0xffffffffu, rm1[mt], 1));
        rm1[mt] = fmaxf(rm1[mt], __shfl_xor_sync(0xffffffffu, rm1[mt], 2));
    }
    if ((lane & 3) == 0) {
        int rr = lane >> 2;
#pragma unroll
        for (int mt = 0; mt < 4; mt++) {
            int ch = mt*16 + rr;
            out[(size_t)i*64 + ch]     = fmaxf(rm0[mt] + b2[ch],     0.f);
            out[(size_t)i*64 + ch + 8] = fmaxf(rm1[mt] + b2[ch + 8], 0.f);
        }
    }
}

// ---------------- launcher ----------------------------------------
extern "C" void kernel_launch(void* const* d_in, const int* in_sizes, int n_in,
                              void* d_out, int out_size) {
    const float* x   = (const float*)d_in[0];
    const float* pos = (const float*)d_in[1];
    // d_in[2] = batch (int32) — recomputed analytically
    const float* W1  = (const float*)d_in[3];
    const float* b1  = (const float*)d_in[4];
    const float* W2  = (const float*)d_in[5];
    const float* b2  = (const float*)d_in[6];
    float* out = (float*)d_out;

    long long off_pos   = (long long)Nn * Hd;
    long long off_batch = off_pos + (long long)Nn * 3;
    long long off_edge  = off_batch + Nn;
    long long need      = off_edge + 2LL * En;
    int write_aux = ((long long)out_size >= need) ? 1 : 0;

    knn_kernel<<<Bev*25, 256>>>(pos, x, W1, b1, out, write_aux, off_pos, off_batch, off_edge);
    mlp3_kernel<<<Nn / 4, 128>>>(W2, b2, out);
}

// round 17
// speedup vs baseline: 2.1810x; 1.0641x over previous
#include <cuda_runtime.h>
#include <cuda_fp16.h>
#include <cstdint>
#include <cfloat>
#include <math_constants.h>

#define Bev 128
#define Pn  200
#define Kn  60
#define Hd  64
#define Nn  (Bev*Pn)          // 25600
#define En  (Nn*Kn)           // 1,536,000

// ---------------- scratch (no cudaMalloc allowed) ----------------
__device__ __align__(16) __half g_uh[Nn*Hd];  // fp16 u = x@W1[:4]+pos@W1[4:]+b1
__device__ __align__(16) __half g_vh[Nn*Hd];  // fp16 v = pos@W1[4:]
__device__ int g_nbr[En];                     // sorted knn neighbor ids

// ================= helpers =========================================
__device__ __forceinline__ uint32_t smem_u32(const void* p) {
    uint32_t a;
    asm("{ .reg .u64 t; cvta.to.shared.u64 t, %1; cvt.u32.u64 %0, t; }" : "=r"(a) : "l"(p));
    return a;
}
__device__ __forceinline__ void ldsm4(uint32_t* r, uint32_t addr) {
    asm volatile("ldmatrix.sync.aligned.m8n8.x4.shared.b16 {%0,%1,%2,%3}, [%4];"
        : "=r"(r[0]), "=r"(r[1]), "=r"(r[2]), "=r"(r[3]) : "r"(addr));
}
__device__ __forceinline__ void mma16816(float* d, const uint32_t* a, const uint32_t* b) {
    asm volatile("mma.sync.aligned.m16n8k16.row.col.f32.f16.f16.f32 "
        "{%0,%1,%2,%3}, {%4,%5,%6,%7}, {%8,%9}, {%0,%1,%2,%3};"
        : "+f"(d[0]), "+f"(d[1]), "+f"(d[2]), "+f"(d[3])
        : "r"(a[0]), "r"(a[1]), "r"(a[2]), "r"(a[3]), "r"(b[0]), "r"(b[1]));
}
__device__ __forceinline__ void cpa16(uint32_t dst, const void* src) {
    asm volatile("cp.async.cg.shared.global [%0], [%1], 16;" :: "r"(dst), "l"(src));
}
__device__ __forceinline__ uint32_t h2bits(__half2 h) {
    return *reinterpret_cast<uint32_t*>(&h);
}
__device__ __forceinline__ unsigned long long u64min(unsigned long long a, unsigned long long b) {
    return (a < b) ? a : b;
}

// ------- kernel 1: fused uv + warp-bitonic top-64 SELECT knn -------------
// Stages k=2..64 leave the four 64-chunks sorted alternately asc/desc
// (standard direction formula). Then bitonic prune+merge twice -> exact
// sorted top-64 (bit-identical selection to the full 256-sort).
__global__ void __launch_bounds__(256, 1)
knn_kernel(const float* __restrict__ pos, const float* __restrict__ x,
           const float* __restrict__ W1, const float* __restrict__ b1,
           float* __restrict__ out,
           int write_aux, long long off_pos, long long off_batch, long long off_edge) {
    __shared__ float spx[Pn], spy[Pn], spz[Pn];
    __shared__ float sW1[7*64];
    __shared__ float sb1[64];
    int blk = blockIdx.x;              // 0..3199
    int b   = blk / 25;                // event
    int q   = blk % 25;                // 8-target group
    int tid = threadIdx.x, lane = tid & 31, warp = tid >> 5;

    for (int t = tid; t < Pn; t += 256) {
        spx[t] = pos[(b*Pn+t)*3+0];
        spy[t] = pos[(b*Pn+t)*3+1];
        spz[t] = pos[(b*Pn+t)*3+2];
    }
    for (int t = tid; t < 7*64; t += 256) sW1[t] = W1[t];
    if (tid < 64) sb1[tid] = b1[tid];
    __syncthreads();

    // ---- uv for this block's 8 nodes (fp16 stores) ----
    for (int e = tid; e < 8*64; e += 256) {
        int nl = e >> 6, c = e & 63;
        int n  = q*8 + nl;
        int gn = b*Pn + n;
        float4 xv = *(const float4*)(x + (size_t)gn*4);
        float a = sb1[c];
        a = fmaf(xv.x, sW1[0*64+c], a);
        a = fmaf(xv.y, sW1[1*64+c], a);
        a = fmaf(xv.z, sW1[2*64+c], a);
        a = fmaf(xv.w, sW1[3*64+c], a);
        float vv = spx[n] * sW1[4*64+c];
        vv = fmaf(spy[n], sW1[5*64+c], vv);
        vv = fmaf(spz[n], sW1[6*64+c], vv);
        g_uh[(size_t)gn*64 + c] = __float2half_rn(a + vv);
        g_vh[(size_t)gn*64 + c] = __float2half_rn(vv);
    }

    // ---- knn: one warp per target ----
    int i  = q*8 + warp;
    int gi = b*Pn + i;
    float pix = spx[i], piy = spy[i], piz = spz[i];

    unsigned long long v[8];
#pragma unroll
    for (int r = 0; r < 7; r++) {
        int j  = r*32 + lane;
        int js = (j < Pn) ? j : 0;
        float dx = spx[js]-pix, dy = spy[js]-piy, dz = spz[js]-piz;
        float d2 = dx*dx; d2 = fmaf(dy,dy,d2); d2 = fmaf(dz,dz,d2);
        bool valid = (j < Pn) && (j != i);
        v[r] = valid ? (((unsigned long long)__float_as_uint(d2) << 32) | (unsigned)j)
                     : ~0ull;
    }
    v[7] = ~0ull;

    // stages k=2..64: chunks of 64 end sorted asc/desc/asc/desc
#pragma unroll
    for (int k = 2; k <= 64; k <<= 1) {
#pragma unroll
        for (int s = 32; s > 0; s >>= 1) {
            if (s >= k) continue;
            if (s == 32) {                       // only at k=64: reg pairs r^1
#pragma unroll
                for (int r = 0; r < 8; r += 2) {
                    bool up = (((r*32) & k) == 0);
                    unsigned long long a  = v[r], bb = v[r+1];
                    bool sw = (a > bb) == up;
                    v[r]   = sw ? bb : a;
                    v[r+1] = sw ? a : bb;
                }
            } else {
#pragma unroll
                for (int r = 0; r < 8; r++) {
                    unsigned long long o = __shfl_xor_sync(0xffffffffu, v[r], s);
                    bool lower = (lane & s) == 0;
                    bool up    = (((r*32 + lane) & k) == 0);
                    unsigned long long mn = (v[r] < o) ? v[r] : o;
                    unsigned long long mx = (v[r] < o) ? o : v[r];
                    v[r] = (lower == up) ? mn : mx;
                }
            }
        }
    }

    // prune 1: bottom-64 of C0||C1 and of C2||C3 (bitonic lower halves)
    unsigned long long m0 = u64min(v[0], v[2]);
    unsigned long long m1 = u64min(v[1], v[3]);
    unsigned long long m2 = u64min(v[4], v[6]);
    unsigned long long m3 = u64min(v[5], v[7]);

    // merge L01 -> sorted asc, L23 -> sorted desc (6 phases on 4 regs)
    {
        unsigned long long a = m0, bb = m1;     // asc: min first
        bool sw = a > bb;
        m0 = sw ? bb : a;  m1 = sw ? a : bb;
        a = m2; bb = m3;                        // desc: max first
        sw = a <= bb;
        m2 = sw ? bb : a;  m3 = sw ? a : bb;
    }
#pragma unroll
    for (int s = 16; s > 0; s >>= 1) {
        bool lower;
        unsigned long long o, mn, mx;
        o = __shfl_xor_sync(0xffffffffu, m0, s); lower = (lane & s) == 0;
        mn = u64min(m0, o); mx = (m0 < o) ? o : m0;
        m0 = lower ? mn : mx;                   // asc
        o = __shfl_xor_sync(0xffffffffu, m1, s);
        mn = u64min(m1, o); mx = (m1 < o) ? o : m1;
        m1 = lower ? mn : mx;                   // asc
        o = __shfl_xor_sync(0xffffffffu, m2, s);
        mn = u64min(m2, o); mx = (m2 < o) ? o : m2;
        m2 = lower ? mx : mn;                   // desc
        o = __shfl_xor_sync(0xffffffffu, m3, s);
        mn = u64min(m3, o); mx = (m3 < o) ? o : m3;
        m3 = lower ? mx : mn;                   // desc
    }

    // prune 2: bottom-64 of L01(asc)||L23(desc)
    unsigned long long f0 = u64min(m0, m2);
    unsigned long long f1 = u64min(m1, m3);

    // final asc merge of bitonic-64 (6 phases on 2 regs)
    {
        unsigned long long a = f0, bb = f1;
        bool sw = a > bb;
        f0 = sw ? bb : a;  f1 = sw ? a : bb;
    }
#pragma unroll
    for (int s = 16; s > 0; s >>= 1) {
        bool lower = (lane & s) == 0;
        unsigned long long o, mn, mx;
        o = __shfl_xor_sync(0xffffffffu, f0, s);
        mn = u64min(f0, o); mx = (f0 < o) ? o : f0;
        f0 = lower ? mn : mx;
        o = __shfl_xor_sync(0xffffffffu, f1, s);
        mn = u64min(f1, o); mx = (f1 < o) ? o : f1;
        f1 = lower ? mn : mx;
    }

    // top-60 = elements 0..59: f0 (t=lane), f1 (t=32+lane, lane<28)
    {
        int j0 = (int)(f0 & 0xffffffffull);
        g_nbr[(size_t)gi*Kn + lane] = b*Pn + j0;
        if (write_aux) {
            out[off_edge +      (long long)gi*Kn + lane] = (float)(b*Pn + j0);
            out[off_edge + En + (long long)gi*Kn + lane] = (float)gi;
        }
        if (lane < Kn - 32) {
            int j1 = (int)(f1 & 0xffffffffull);
            g_nbr[(size_t)gi*Kn + 32 + lane] = b*Pn + j1;
            if (write_aux) {
                out[off_edge +      (long long)gi*Kn + 32 + lane] = (float)(b*Pn + j1);
                out[off_edge + En + (long long)gi*Kn + 32 + lane] = (float)gi;
            }
        }
        if (lane == 0 && write_aux) {
            out[off_pos + (long long)gi*3+0] = pix;
            out[off_pos + (long long)gi*3+1] = piy;
            out[off_pos + (long long)gi*3+2] = piz;
            out[off_batch + gi] = (float)b;
        }
    }
}

// ---------------- kernel 2: HMMA mlp + fused max-aggregate --------
// (byte-exact round-16 version — known good at 63.3us, rel_err 2.57e-4)
__global__ void __launch_bounds__(128)
mlp3_kernel(const float* __restrict__ W2, const float* __restrict__ b2,
            float* __restrict__ out) {
    __shared__ __align__(16) __half sW[64][72];       // W2^T hi
    __shared__ __align__(16) __half sU[4][2][8][88];  // [warp][stage][row][64+pad]
    int tid = threadIdx.x, lane = tid & 31, warp = tid >> 5;

    for (int e = tid; e < 64*64; e += 128) {
        int k = e >> 6, ch = e & 63;
        sW[ch][k] = __float2half_rn(W2[k*64 + ch]);
    }
    __syncthreads();

    const int r = (lane & 7) + ((lane >> 3) & 1) * 8;
    const int c = ((lane >> 4) & 1) * 8;

    uint32_t aH[4][4][4];
#pragma unroll
    for (int mt = 0; mt < 4; mt++)
#pragma unroll
        for (int kt = 0; kt < 4; kt++)
            ldsm4(aH[mt][kt], smem_u32(&sW[mt*16 + r][kt*16 + c]));

    int i = blockIdx.x * 4 + warp;                    // node id
    const int cb = (lane & 3) * 2;                    // k base within k-tile
    const int mrow = lane >> 2;                       // message row in group
    const int seg  = lane & 7;                        // 16B chunk within 128B row
    const int rq   = lane >> 3;                       // row quarter for prefetch

    int nA = g_nbr[(size_t)i*Kn + lane];
    int nB = (lane < Kn - 32) ? g_nbr[(size_t)i*Kn + 32 + lane] : 0;

    const uint32_t suBase = smem_u32(&sU[warp][0][0][0]);   // stage stride 1408B

    const __half2 hzero = __floats2half2_rn(0.f, 0.f);
    __half2 vA2[4], vB2[4];
#pragma unroll
    for (int kt = 0; kt < 4; kt++) {
        vA2[kt] = *(const __half2*)(g_vh + (size_t)i*64 + kt*16 + cb);
        vB2[kt] = *(const __half2*)(g_vh + (size_t)i*64 + kt*16 + cb + 8);
    }

    float rm0[4], rm1[4];
#pragma unroll
    for (int mt = 0; mt < 4; mt++) { rm0[mt] = -FLT_MAX; rm1[mt] = -FLT_MAX; }

#define PREFETCH_GRP(gg, st) do {                                            \
        _Pragma("unroll")                                                    \
        for (int it = 0; it < 2; it++) {                                     \
            int rr = it*4 + rq;                                              \
            int mm = (gg)*8 + rr;                                            \
            int jj = (mm < 32) ? __shfl_sync(0xffffffffu, nA, mm)            \
                   : (mm < Kn) ? __shfl_sync(0xffffffffu, nB, mm - 32)       \
                   : i;                                                      \
            cpa16(suBase + (st)*1408 + rr*176 + seg*16,                      \
                  (const char*)g_uh + (size_t)jj*128 + seg*16);              \
        }                                                                    \
        asm volatile("cp.async.commit_group;" ::: "memory");                 \
    } while (0)

    PREFETCH_GRP(0, 0);

    for (int g = 0; g < 8; g++) {                     // 8 groups of 8 messages
        if (g < 7) {
            PREFETCH_GRP(g+1, (g+1)&1);
            asm volatile("cp.async.wait_group 1;" ::: "memory");
        } else {
            asm volatile("cp.async.wait_group 0;" ::: "memory");
        }
        __syncwarp();

        const __half* su = &sU[warp][g & 1][0][0];
        uint32_t bH[4][2];
#pragma unroll
        for (int kt = 0; kt < 4; kt++) {
            __half2 ua = *(const __half2*)(su + mrow*88 + kt*16 + cb);
            __half2 ub = *(const __half2*)(su + mrow*88 + kt*16 + cb + 8);
            bH[kt][0] = h2bits(__hmax2(__hsub2(ua, vA2[kt]), hzero));
            bH[kt][1] = h2bits(__hmax2(__hsub2(ub, vB2[kt]), hzero));
        }

#pragma unroll
        for (int mt = 0; mt < 4; mt++) {
            float dh[4] = {0,0,0,0};
#pragma unroll
            for (int kt = 0; kt < 4; kt++)
                mma16816(dh, aH[mt][kt], bH[kt]);
            rm0[mt] = fmaxf(rm0[mt], fmaxf(dh[0], dh[1]));
            rm1[mt] = fmaxf(rm1[mt], fmaxf(dh[2], dh[3]));
        }
        __syncwarp();   // reads of this stage done before next prefetch lands
    }

#pragma unroll
    for (int mt = 0; mt < 4; mt++) {
        rm0[mt] = fmaxf(rm0[mt], __shfl_xor_sync(0xffffffffu, rm0[mt], 1));
        rm0[mt] = fmaxf(rm0[mt], __shfl_xor_sync(0xffffffffu, rm0[mt], 2));
        rm1[mt] = fmaxf(rm1[mt], __shfl_xor_sync(0xffffffffu, rm1[mt], 1));
        rm1[mt] = fmaxf(rm1[mt], __shfl_xor_sync(0xffffffffu, rm1[mt], 2));
    }
    if ((lane & 3) == 0) {
        int rr = lane >> 2;
#pragma unroll
        for (int mt = 0; mt < 4; mt++) {
            int ch = mt*16 + rr;
            out[(size_t)i*64 + ch]     = fmaxf(rm0[mt] + b2[ch],     0.f);
            out[(size_t)i*64 + ch + 8] = fmaxf(rm1[mt] + b2[ch + 8], 0.f);
        }
    }
}

// ---------------- launcher ----------------------------------------
extern "C" void kernel_launch(void* const* d_in, const int* in_sizes, int n_in,
                              void* d_out, int out_size) {
    const float* x   = (const float*)d_in[0];
    const float* pos = (const float*)d_in[1];
    // d_in[2] = batch (int32) — recomputed analytically
    const float* W1  = (const float*)d_in[3];
    const float* b1  = (const float*)d_in[4];
    const float* W2  = (const float*)d_in[5];
    const float* b2  = (const float*)d_in[6];
    float* out = (float*)d_out;

    long long off_pos   = (long long)Nn * Hd;
    long long off_batch = off_pos + (long long)Nn * 3;
    long long off_edge  = off_batch + Nn;
    long long need      = off_edge + 2LL * En;
    int write_aux = ((long long)out_size >= need) ? 1 : 0;

    knn_kernel<<<Bev*25, 256>>>(pos, x, W1, b1, out, write_aux, off_pos, off_batch, off_edge);
    mlp3_kernel<<<Nn / 4, 128>>>(W2, b2, out);
}